// round 4
// baseline (speedup 1.0000x reference)
#include <cuda_runtime.h>

// Problem constants
// B=2, S=2048, D_IN=2048, D_OUT=2048, H=32 heads, G=8 kv groups, R=4, D=64
#define SEQ    2048
#define DMODEL 2048
#define NHEAD  32
#define NGRP   8
#define HDIM   64

#define OUT_ELEMS  (2ull * SEQ * DMODEL)          // 8388608
#define KV_ELEMS   (2ull * NGRP * SEQ * HDIM)     // 2097152

// Scratch (allocation-free rule: __device__ globals; referenced directly from
// device code so kernel_launch needs NO cudaGetSymbolAddress)
__device__ float g_Q  [2ull * SEQ * DMODEL];   // [b*S, 2048] col = h*64+d
__device__ float g_ctx[2ull * SEQ * DMODEL];   // [b*S, 2048]

// ---------------------------------------------------------------------------
// Tiled SGEMM: C[M,N] = A[M,K] @ W[N,K]^T   (torch-style weight layout)
// 64x64 tile, BK=16, 256 threads, 4x4 register micro-tile.
// Smem stored k-major (As[kk][m]) so inner loop is 2x LDS.128 + 16 FFMA.
// SRC  0: A = param.  1: A = g_ctx (device global).
// MODE 0: C = param, row-major [M,N].
//      1: C = param, kv-cache layout: m=(b*S+s), n=(g*64+d)
//         -> C[((b*8+g)*S+s)*64+d]
//      2: C = g_Q (device global), row-major [M,N].
// ---------------------------------------------------------------------------
template<int SRC, int MODE>
__global__ void __launch_bounds__(256) gemm64(const float* __restrict__ A,
                                              const float* __restrict__ W,
                                              float* __restrict__ C,
                                              int M, int N, int K) {
    __shared__ float As[16 * 64];
    __shared__ float Ws[16 * 64];
    const float* Asrc = (SRC == 1) ? (const float*)g_ctx : A;
    float*       Cdst = (MODE == 2) ? (float*)g_Q : C;

    const int tid = threadIdx.x;
    const int tx = tid & 15, ty = tid >> 4;
    const int m0 = blockIdx.y * 64, n0 = blockIdx.x * 64;
    const int lr = tid >> 2;           // 0..63  tile row
    const int lc = (tid & 3) << 2;     // 0,4,8,12 k offset
    const float* Ag = Asrc + (size_t)(m0 + lr) * K + lc;
    const float* Wg = W    + (size_t)(n0 + lr) * K + lc;

    float acc[4][4] = {};
    for (int k0 = 0; k0 < K; k0 += 16) {
        float4 av = *(const float4*)(Ag + k0);
        float4 wv = *(const float4*)(Wg + k0);
        __syncthreads();   // previous iteration's reads done
        As[(lc + 0) * 64 + lr] = av.x;
        As[(lc + 1) * 64 + lr] = av.y;
        As[(lc + 2) * 64 + lr] = av.z;
        As[(lc + 3) * 64 + lr] = av.w;
        Ws[(lc + 0) * 64 + lr] = wv.x;
        Ws[(lc + 1) * 64 + lr] = wv.y;
        Ws[(lc + 2) * 64 + lr] = wv.z;
        Ws[(lc + 3) * 64 + lr] = wv.w;
        __syncthreads();
        #pragma unroll
        for (int kk = 0; kk < 16; kk++) {
            float4 a4 = *(const float4*)&As[kk * 64 + 4 * ty];
            float4 b4 = *(const float4*)&Ws[kk * 64 + 4 * tx];
            float ar[4] = {a4.x, a4.y, a4.z, a4.w};
            float br[4] = {b4.x, b4.y, b4.z, b4.w};
            #pragma unroll
            for (int i = 0; i < 4; i++)
                #pragma unroll
                for (int j = 0; j < 4; j++)
                    acc[i][j] = fmaf(ar[i], br[j], acc[i][j]);
        }
    }

    #pragma unroll
    for (int i = 0; i < 4; i++) {
        int m = m0 + 4 * ty + i;
        float4 o = make_float4(acc[i][0], acc[i][1], acc[i][2], acc[i][3]);
        if (MODE == 1) {
            // n0 is a multiple of 64 -> g = n0>>6 constant for the block
            int b = m >> 11, s = m & 2047;
            int g = n0 >> 6;
            *(float4*)&Cdst[(((size_t)(b * NGRP + g)) * SEQ + s) * HDIM + 4 * tx] = o;
        } else {
            *(float4*)&Cdst[(size_t)m * N + n0 + 4 * tx] = o;
        }
    }
}

// ---------------------------------------------------------------------------
// Flash attention (causal), fp32, STATIC shared memory (42.4 KB, no opt-in).
// One CTA per (b, head, 64-row q tile). 32-wide key tiles, online softmax,
// 4x4 register accumulators (64 output dims), S tile 64x32.
// Reads K/V from the kv-cache region of d_out ([b,g,s,d] layout).
// Reads Q from g_Q, writes ctx to g_ctx (direct global references).
// ---------------------------------------------------------------------------
__global__ void __launch_bounds__(256) attn64(const float* __restrict__ keys,
                                              const float* __restrict__ vals) {
    __shared__ float Qs[64 * 65];    // padded: 2 rows/warp read at fixed d
    __shared__ float Ks[32 * 65];    // padded: 16 rows read at fixed d
    __shared__ float Vs[32 * 64];    // read 64-consecutive per kk: no pad
    __shared__ float Ss[64 * 33];    // padded rows of 32 + 1
    __shared__ float mrow[64], lrow[64], srow[64];

    const int tid = threadIdx.x;
    const int tx = tid & 15, ty = tid >> 4;
    const int qt = blockIdx.x;            // 0..31
    const int b  = blockIdx.y >> 5;       // 0..1
    const int h  = blockIdx.y & 31;       // 0..31
    const int g  = h >> 2;
    const int q0 = qt * 64;

    const float* Qg = g_Q + ((size_t)(b * SEQ + q0)) * DMODEL + h * HDIM;
    for (int i = tid; i < 4096; i += 256) {
        int r = i >> 6, d = i & 63;
        Qs[r * 65 + d] = Qg[(size_t)r * DMODEL + d];
    }
    if (tid < 64) { mrow[tid] = -1e30f; lrow[tid] = 0.f; }

    float acc[4][4] = {};
    const float* Kg = keys + (size_t)(b * NGRP + g) * SEQ * HDIM;
    const float* Vg = vals + (size_t)(b * NGRP + g) * SEQ * HDIM;

    const int njt = 2 * qt + 2;           // 32-wide k tiles covering [0, q0+64)
    for (int jt = 0; jt < njt; jt++) {
        __syncthreads();  // prior iteration done with Ks/Vs/Ss (and Q/stat init)
        const int j0 = jt * 32;
        for (int i = tid; i < 2048; i += 256) {
            int r = i >> 6, d = i & 63;
            Ks[r * 65 + d] = Kg[(size_t)(j0 + r) * HDIM + d];
            Vs[r * 64 + d] = Vg[(size_t)(j0 + r) * HDIM + d];
        }
        __syncthreads();

        // S[64x32] = Q K^T * 1/sqrt(64); thread owns rows 4ty+i, cols 2tx+jj
        float s[4][2] = {};
        #pragma unroll 8
        for (int d = 0; d < 64; d++) {
            float a[4], bb[2];
            #pragma unroll
            for (int i = 0; i < 4; i++) a[i] = Qs[(4 * ty + i) * 65 + d];
            #pragma unroll
            for (int jj = 0; jj < 2; jj++) bb[jj] = Ks[(2 * tx + jj) * 65 + d];
            #pragma unroll
            for (int i = 0; i < 4; i++)
                #pragma unroll
                for (int jj = 0; jj < 2; jj++)
                    s[i][jj] = fmaf(a[i], bb[jj], s[i][jj]);
        }
        #pragma unroll
        for (int i = 0; i < 4; i++)
            #pragma unroll
            for (int jj = 0; jj < 2; jj++) {
                float v = s[i][jj] * 0.125f;
                if (j0 + 2 * tx + jj > q0 + 4 * ty + i) v = -1e30f;
                Ss[(4 * ty + i) * 33 + 2 * tx + jj] = v;
            }
        __syncthreads();

        // Online softmax: one thread per row (32 columns)
        if (tid < 64) {
            float mo = mrow[tid];
            float mx = mo;
            #pragma unroll 8
            for (int c = 0; c < 32; c++) mx = fmaxf(mx, Ss[tid * 33 + c]);
            float sum = 0.f;
            #pragma unroll 8
            for (int c = 0; c < 32; c++) {
                float p = __expf(Ss[tid * 33 + c] - mx);
                Ss[tid * 33 + c] = p;
                sum += p;
            }
            float sc = __expf(mo - mx);
            mrow[tid] = mx;
            lrow[tid] = lrow[tid] * sc + sum;
            srow[tid] = sc;
        }
        __syncthreads();

        // Rescale accumulators, then acc += P[64x32] @ V[32x64]
        #pragma unroll
        for (int i = 0; i < 4; i++) {
            float sc = srow[4 * ty + i];
            #pragma unroll
            for (int j = 0; j < 4; j++) acc[i][j] *= sc;
        }
        #pragma unroll 8
        for (int kk = 0; kk < 32; kk++) {
            float p[4], vv[4];
            #pragma unroll
            for (int i = 0; i < 4; i++) p[i] = Ss[(4 * ty + i) * 33 + kk];
            #pragma unroll
            for (int j = 0; j < 4; j++) vv[j] = Vs[kk * 64 + 4 * tx + j];
            #pragma unroll
            for (int i = 0; i < 4; i++)
                #pragma unroll
                for (int j = 0; j < 4; j++)
                    acc[i][j] = fmaf(p[i], vv[j], acc[i][j]);
        }
    }

    // Final normalize + store to ctx [b*S, 2048] (col = h*64+d)
    #pragma unroll
    for (int i = 0; i < 4; i++) {
        int r = 4 * ty + i;
        float inv = 1.f / lrow[r];
        float4 o = make_float4(acc[i][0] * inv, acc[i][1] * inv,
                               acc[i][2] * inv, acc[i][3] * inv);
        *(float4*)&g_ctx[((size_t)(b * SEQ + q0 + r)) * DMODEL + h * HDIM + 4 * tx] = o;
    }
}

// ---------------------------------------------------------------------------
// Launch: kernel launches ONLY — no other CUDA API calls (clean graph capture)
// ---------------------------------------------------------------------------
extern "C" void kernel_launch(void* const* d_in, const int* in_sizes, int n_in,
                              void* d_out, int out_size) {
    const float* x  = (const float*)d_in[0];
    const float* Wq = (const float*)d_in[1];
    const float* Wk = (const float*)d_in[2];
    const float* Wv = (const float*)d_in[3];
    const float* Wo = (const float*)d_in[4];

    float* out  = (float*)d_out;
    float* keys = out + OUT_ELEMS;             // [b,g,s,d]
    float* vals = keys + KV_ELEMS;             // [b,g,s,d]

    const int M = 2 * SEQ;                     // 4096

    // Q projection -> g_Q (row-major, col = h*64+d)
    gemm64<0, 2><<<dim3(DMODEL / 64, M / 64), 256>>>(x, Wq, nullptr, M, DMODEL, DMODEL);
    // K/V projections -> directly into d_out kv-cache region ([b,g,s,d])
    gemm64<0, 1><<<dim3((NGRP * HDIM) / 64, M / 64), 256>>>(x, Wk, keys, M, NGRP * HDIM, DMODEL);
    gemm64<0, 1><<<dim3((NGRP * HDIM) / 64, M / 64), 256>>>(x, Wv, vals, M, NGRP * HDIM, DMODEL);
    // Causal flash attention: g_Q x (keys,vals) -> g_ctx
    attn64<<<dim3(SEQ / 64, 2 * NHEAD), 256>>>(keys, vals);
    // Output projection: g_ctx @ Wo^T -> d_out
    gemm64<1, 0><<<dim3(DMODEL / 64, M / 64), 256>>>(nullptr, Wo, out, M, DMODEL, DMODEL);
}

// round 8
// speedup vs baseline: 1.5722x; 1.5722x over previous
#include <cuda_runtime.h>
#include <cuda_bf16.h>
#include <cstdint>

// Problem constants
// B=2, S=2048, D_IN=2048, D_OUT=2048, H=32 heads, G=8 kv groups, R=4, D=64
#define SEQ    2048
#define DMODEL 2048
#define NHEAD  32
#define NGRP   8
#define HDIM   64
#define KDIM   2048

#define OUT_ELEMS  (2ull * SEQ * DMODEL)          // 8388608
#define KV_ELEMS   (2ull * NGRP * SEQ * HDIM)     // 2097152
#define MROWS      (2 * SEQ)                      // 4096

// ---------------- device-global scratch (allocation-free rule) --------------
__device__ float g_Q  [ (size_t)MROWS * DMODEL ];   // fp32 Q proj
__device__ float g_ctx[ (size_t)MROWS * DMODEL ];   // fp32 attention output
// bf16 split operands
__device__ __nv_bfloat16 g_xhi[(size_t)MROWS * DMODEL];
__device__ __nv_bfloat16 g_xlo[(size_t)MROWS * DMODEL];
__device__ __nv_bfloat16 g_whi[(size_t)DMODEL * DMODEL];
__device__ __nv_bfloat16 g_wlo[(size_t)DMODEL * DMODEL];
__device__ __nv_bfloat16 g_chi[(size_t)MROWS * DMODEL];
__device__ __nv_bfloat16 g_clo[(size_t)MROWS * DMODEL];

// ---------------------------------------------------------------------------
// fp32 -> bf16 hi/lo split. DST: 0 = x buffers, 1 = w buffers,
// 2 = ctx buffers (src = g_ctx internally).
// ---------------------------------------------------------------------------
template<int DST>
__global__ void __launch_bounds__(256) cvt_split(const float* __restrict__ srcp, int n4) {
    const float4* s = (const float4*)(DST == 2 ? (const float*)g_ctx : srcp);
    uint2* hp = (uint2*)(DST == 0 ? g_xhi : DST == 1 ? g_whi : g_chi);
    uint2* lp = (uint2*)(DST == 0 ? g_xlo : DST == 1 ? g_wlo : g_clo);
    for (int i = blockIdx.x * blockDim.x + threadIdx.x; i < n4;
         i += gridDim.x * blockDim.x) {
        float4 v = s[i];
        __nv_bfloat16 h0 = __float2bfloat16(v.x);
        __nv_bfloat16 h1 = __float2bfloat16(v.y);
        __nv_bfloat16 h2 = __float2bfloat16(v.z);
        __nv_bfloat16 h3 = __float2bfloat16(v.w);
        __nv_bfloat16 l0 = __float2bfloat16(v.x - __bfloat162float(h0));
        __nv_bfloat16 l1 = __float2bfloat16(v.y - __bfloat162float(h1));
        __nv_bfloat16 l2 = __float2bfloat16(v.z - __bfloat162float(h2));
        __nv_bfloat16 l3 = __float2bfloat16(v.w - __bfloat162float(h3));
        __nv_bfloat162 h01{h0, h1}, h23{h2, h3}, l01{l0, l1}, l23{l2, l3};
        uint2 hu{*(uint32_t*)&h01, *(uint32_t*)&h23};
        uint2 lu{*(uint32_t*)&l01, *(uint32_t*)&l23};
        hp[i] = hu;
        lp[i] = lu;
    }
}

// ---------------------------------------------------------------------------
// mma.sync helper: D += A * B  (m16n8k16, bf16 in, fp32 acc)
// ---------------------------------------------------------------------------
__device__ __forceinline__ void mma16816(float* d, const uint32_t* a, const uint32_t* b) {
    asm volatile(
        "mma.sync.aligned.m16n8k16.row.col.f32.bf16.bf16.f32 "
        "{%0,%1,%2,%3}, {%4,%5,%6,%7}, {%8,%9}, {%0,%1,%2,%3};\n"
        : "+f"(d[0]), "+f"(d[1]), "+f"(d[2]), "+f"(d[3])
        : "r"(a[0]), "r"(a[1]), "r"(a[2]), "r"(a[3]), "r"(b[0]), "r"(b[1]));
}

// ---------------------------------------------------------------------------
// Split-bf16 tensor-core GEMM via mma.sync: C[M,N] = A @ W^T with
// Ahi*Whi + Alo*Whi + Ahi*Wlo accumulated in fp32 registers.
// CTA tile 128x128, 8 warps (warp tile 32x64), BK=16, 2-stage smem
// double buffer (exactly 48 KB static), register-staged global loads.
// AB: 0 = A from g_xhi/g_xlo, 1 = A from g_chi/g_clo.
// OM: 0 = C row-major param. 1 = kv-cache layout param. 2 = g_Q row-major.
// ---------------------------------------------------------------------------
#define LDK   24          // smem row stride in halves (16 data + 8 pad)
#define TILE_H (128 * LDK)             // halves per tile (3072)
#define STAGE_H (4 * TILE_H)           // Ahi,Alo,Whi,Wlo (12288)

template<int AB, int OM>
__global__ void __launch_bounds__(256) gemm_mma(float* __restrict__ C, int N) {
    __shared__ __nv_bfloat16 smbuf[2 * STAGE_H];   // 49152 bytes exactly

    const int tid  = threadIdx.x;
    const int wid  = tid >> 5;
    const int lane = tid & 31;
    const int g    = lane >> 2;        // 0..7
    const int tq   = lane & 3;         // 0..3
    const int m0 = blockIdx.y * 128;
    const int n0 = blockIdx.x * 128;
    const int m_off = (wid & 3) * 32;  // warp M offset
    const int n_off = (wid >> 2) * 64; // warp N offset

    const __nv_bfloat16* __restrict__ Ahi = AB ? g_chi : g_xhi;
    const __nv_bfloat16* __restrict__ Alo = AB ? g_clo : g_xlo;

    // copy addressing: each thread moves one uint4 (8 halves) per tile per chunk
    const int r_cp = tid >> 1;         // 0..127
    const int h_cp = (tid & 1) * 8;    // 0 or 8 halves
    const size_t gA = (size_t)(m0 + r_cp) * KDIM + h_cp;
    const size_t gW = (size_t)(n0 + r_cp) * KDIM + h_cp;
    const int s_cp = r_cp * LDK + h_cp;

    float acc[2][8][4] = {};
    uint4 stg[4];

    // prologue: load chunk 0
    stg[0] = *(const uint4*)&Ahi  [gA];
    stg[1] = *(const uint4*)&Alo  [gA];
    stg[2] = *(const uint4*)&g_whi[gW];
    stg[3] = *(const uint4*)&g_wlo[gW];
    {
        __nv_bfloat16* st0 = smbuf;    // stage 0
        *(uint4*)&st0[0 * TILE_H + s_cp] = stg[0];
        *(uint4*)&st0[1 * TILE_H + s_cp] = stg[1];
        *(uint4*)&st0[2 * TILE_H + s_cp] = stg[2];
        *(uint4*)&st0[3 * TILE_H + s_cp] = stg[3];
    }

    const int NCH = KDIM / 16;         // 128 chunks
    for (int c = 0; c < NCH; c++) {
        __syncthreads();               // stage c&1 ready; stage (c+1)&1 free

        if (c + 1 < NCH) {
            const size_t ko = (size_t)(c + 1) * 16;
            stg[0] = *(const uint4*)&Ahi  [gA + ko];
            stg[1] = *(const uint4*)&Alo  [gA + ko];
            stg[2] = *(const uint4*)&g_whi[gW + ko];
            stg[3] = *(const uint4*)&g_wlo[gW + ko];
        }

        // ---- compute on stage c&1 ----
        const __nv_bfloat16* Sb  = smbuf + (c & 1) * STAGE_H;
        const __nv_bfloat16* Sah = Sb;
        const __nv_bfloat16* Sal = Sb + TILE_H;
        const __nv_bfloat16* Swh = Sb + 2 * TILE_H;
        const __nv_bfloat16* Swl = Sb + 3 * TILE_H;
        const int kb = 2 * tq;         // 0,2,4,6

        uint32_t ah[2][4], al[2][4], wh[8][2], wl[8][2];
        #pragma unroll
        for (int mi = 0; mi < 2; mi++) {
            const int r = m_off + mi * 16 + g;
            ah[mi][0] = *(const uint32_t*)&Sah[r * LDK + kb];
            ah[mi][1] = *(const uint32_t*)&Sah[(r + 8) * LDK + kb];
            ah[mi][2] = *(const uint32_t*)&Sah[r * LDK + kb + 8];
            ah[mi][3] = *(const uint32_t*)&Sah[(r + 8) * LDK + kb + 8];
            al[mi][0] = *(const uint32_t*)&Sal[r * LDK + kb];
            al[mi][1] = *(const uint32_t*)&Sal[(r + 8) * LDK + kb];
            al[mi][2] = *(const uint32_t*)&Sal[r * LDK + kb + 8];
            al[mi][3] = *(const uint32_t*)&Sal[(r + 8) * LDK + kb + 8];
        }
        #pragma unroll
        for (int ni = 0; ni < 8; ni++) {
            const int r = n_off + ni * 8 + g;
            wh[ni][0] = *(const uint32_t*)&Swh[r * LDK + kb];
            wh[ni][1] = *(const uint32_t*)&Swh[r * LDK + kb + 8];
            wl[ni][0] = *(const uint32_t*)&Swl[r * LDK + kb];
            wl[ni][1] = *(const uint32_t*)&Swl[r * LDK + kb + 8];
        }
        #pragma unroll
        for (int mi = 0; mi < 2; mi++)
            #pragma unroll
            for (int ni = 0; ni < 8; ni++)
                mma16816(acc[mi][ni], ah[mi], wh[ni]);
        #pragma unroll
        for (int mi = 0; mi < 2; mi++)
            #pragma unroll
            for (int ni = 0; ni < 8; ni++)
                mma16816(acc[mi][ni], al[mi], wh[ni]);
        #pragma unroll
        for (int mi = 0; mi < 2; mi++)
            #pragma unroll
            for (int ni = 0; ni < 8; ni++)
                mma16816(acc[mi][ni], ah[mi], wl[ni]);

        // ---- store next chunk into the other stage ----
        if (c + 1 < NCH) {
            __nv_bfloat16* st = smbuf + ((c + 1) & 1) * STAGE_H;
            *(uint4*)&st[0 * TILE_H + s_cp] = stg[0];
            *(uint4*)&st[1 * TILE_H + s_cp] = stg[1];
            *(uint4*)&st[2 * TILE_H + s_cp] = stg[2];
            *(uint4*)&st[3 * TILE_H + s_cp] = stg[3];
        }
    }

    // ---- epilogue: c0,c1 -> (row g, cols 2tq,2tq+1); c2,c3 -> row g+8 ----
    float* Cd = (OM == 2) ? (float*)g_Q : C;
    #pragma unroll
    for (int mi = 0; mi < 2; mi++) {
        #pragma unroll
        for (int ni = 0; ni < 8; ni++) {
            const int nloc = n_off + ni * 8 + 2 * tq;
            #pragma unroll
            for (int h2 = 0; h2 < 2; h2++) {
                const int m = m0 + m_off + mi * 16 + g + h2 * 8;
                float2 v = make_float2(acc[mi][ni][h2 * 2], acc[mi][ni][h2 * 2 + 1]);
                if (OM == 1) {
                    const int bb = m >> 11, s = m & 2047;
                    const int gg = (n0 + nloc) >> 6;
                    const int d  = (n0 + nloc) & 63;
                    *(float2*)&Cd[(((size_t)(bb * NGRP + gg)) * SEQ + s) * HDIM + d] = v;
                } else {
                    *(float2*)&Cd[(size_t)m * N + n0 + nloc] = v;
                }
            }
        }
    }
}

// ---------------------------------------------------------------------------
// Flash attention (causal), fp32, static smem (unchanged from passing R4).
// ---------------------------------------------------------------------------
__global__ void __launch_bounds__(256) attn64(const float* __restrict__ keys,
                                              const float* __restrict__ vals) {
    __shared__ float Qs[64 * 65];
    __shared__ float Ks[32 * 65];
    __shared__ float Vs[32 * 64];
    __shared__ float Ss[64 * 33];
    __shared__ float mrow[64], lrow[64], srow[64];

    const int tid = threadIdx.x;
    const int tx = tid & 15, ty = tid >> 4;
    const int qt = blockIdx.x;
    const int b  = blockIdx.y >> 5;
    const int h  = blockIdx.y & 31;
    const int g  = h >> 2;
    const int q0 = qt * 64;

    const float* Qg = g_Q + ((size_t)(b * SEQ + q0)) * DMODEL + h * HDIM;
    for (int i = tid; i < 4096; i += 256) {
        int r = i >> 6, d = i & 63;
        Qs[r * 65 + d] = Qg[(size_t)r * DMODEL + d];
    }
    if (tid < 64) { mrow[tid] = -1e30f; lrow[tid] = 0.f; }

    float acc[4][4] = {};
    const float* Kg = keys + (size_t)(b * NGRP + g) * SEQ * HDIM;
    const float* Vg = vals + (size_t)(b * NGRP + g) * SEQ * HDIM;

    const int njt = 2 * qt + 2;
    for (int jt = 0; jt < njt; jt++) {
        __syncthreads();
        const int j0 = jt * 32;
        for (int i = tid; i < 2048; i += 256) {
            int r = i >> 6, d = i & 63;
            Ks[r * 65 + d] = Kg[(size_t)(j0 + r) * HDIM + d];
            Vs[r * 64 + d] = Vg[(size_t)(j0 + r) * HDIM + d];
        }
        __syncthreads();

        float s[4][2] = {};
        #pragma unroll 8
        for (int d = 0; d < 64; d++) {
            float a[4], bb[2];
            #pragma unroll
            for (int i = 0; i < 4; i++) a[i] = Qs[(4 * ty + i) * 65 + d];
            #pragma unroll
            for (int jj = 0; jj < 2; jj++) bb[jj] = Ks[(2 * tx + jj) * 65 + d];
            #pragma unroll
            for (int i = 0; i < 4; i++)
                #pragma unroll
                for (int jj = 0; jj < 2; jj++)
                    s[i][jj] = fmaf(a[i], bb[jj], s[i][jj]);
        }
        #pragma unroll
        for (int i = 0; i < 4; i++)
            #pragma unroll
            for (int jj = 0; jj < 2; jj++) {
                float v = s[i][jj] * 0.125f;
                if (j0 + 2 * tx + jj > q0 + 4 * ty + i) v = -1e30f;
                Ss[(4 * ty + i) * 33 + 2 * tx + jj] = v;
            }
        __syncthreads();

        if (tid < 64) {
            float mo = mrow[tid];
            float mx = mo;
            #pragma unroll 8
            for (int c = 0; c < 32; c++) mx = fmaxf(mx, Ss[tid * 33 + c]);
            float sum = 0.f;
            #pragma unroll 8
            for (int c = 0; c < 32; c++) {
                float p = __expf(Ss[tid * 33 + c] - mx);
                Ss[tid * 33 + c] = p;
                sum += p;
            }
            float sc = __expf(mo - mx);
            mrow[tid] = mx;
            lrow[tid] = lrow[tid] * sc + sum;
            srow[tid] = sc;
        }
        __syncthreads();

        #pragma unroll
        for (int i = 0; i < 4; i++) {
            float sc = srow[4 * ty + i];
            #pragma unroll
            for (int j = 0; j < 4; j++) acc[i][j] *= sc;
        }
        #pragma unroll 8
        for (int kk = 0; kk < 32; kk++) {
            float p[4], vv[4];
            #pragma unroll
            for (int i = 0; i < 4; i++) p[i] = Ss[(4 * ty + i) * 33 + kk];
            #pragma unroll
            for (int j = 0; j < 4; j++) vv[j] = Vs[kk * 64 + 4 * tx + j];
            #pragma unroll
            for (int i = 0; i < 4; i++)
                #pragma unroll
                for (int j = 0; j < 4; j++)
                    acc[i][j] = fmaf(p[i], vv[j], acc[i][j]);
        }
    }

    #pragma unroll
    for (int i = 0; i < 4; i++) {
        int r = 4 * ty + i;
        float inv = 1.f / lrow[r];
        float4 o = make_float4(acc[i][0] * inv, acc[i][1] * inv,
                               acc[i][2] * inv, acc[i][3] * inv);
        *(float4*)&g_ctx[((size_t)(b * SEQ + q0 + r)) * DMODEL + h * HDIM + 4 * tx] = o;
    }
}

// ---------------------------------------------------------------------------
// Launch: kernel launches ONLY
// ---------------------------------------------------------------------------
extern "C" void kernel_launch(void* const* d_in, const int* in_sizes, int n_in,
                              void* d_out, int out_size) {
    const float* x  = (const float*)d_in[0];
    const float* Wq = (const float*)d_in[1];
    const float* Wk = (const float*)d_in[2];
    const float* Wv = (const float*)d_in[3];
    const float* Wo = (const float*)d_in[4];

    float* out  = (float*)d_out;
    float* keys = out + OUT_ELEMS;             // [b,g,s,d]
    float* vals = keys + KV_ELEMS;             // [b,g,s,d]

    // x -> bf16 hi/lo
    cvt_split<0><<<2048, 256>>>(x, (int)(MROWS * DMODEL / 4));
    // Q = x @ Wq^T -> g_Q
    cvt_split<1><<<2048, 256>>>(Wq, DMODEL * DMODEL / 4);
    gemm_mma<0, 2><<<dim3(DMODEL / 128, MROWS / 128), 256>>>(nullptr, DMODEL);
    // K = x @ Wk^T -> keys (kv layout)
    cvt_split<1><<<2048, 256>>>(Wk, NGRP * HDIM * DMODEL / 4);
    gemm_mma<0, 1><<<dim3(NGRP * HDIM / 128, MROWS / 128), 256>>>(keys, NGRP * HDIM);
    // V = x @ Wv^T -> vals
    cvt_split<1><<<2048, 256>>>(Wv, NGRP * HDIM * DMODEL / 4);
    gemm_mma<0, 1><<<dim3(NGRP * HDIM / 128, MROWS / 128), 256>>>(vals, NGRP * HDIM);
    // Attention
    attn64<<<dim3(SEQ / 64, 2 * NHEAD), 256>>>(keys, vals);
    // ctx -> bf16 hi/lo ; out = ctx @ Wo^T
    cvt_split<2><<<2048, 256>>>(nullptr, (int)(MROWS * DMODEL / 4));
    cvt_split<1><<<2048, 256>>>(Wo, DMODEL * DMODEL / 4);
    gemm_mma<1, 0><<<dim3(DMODEL / 128, MROWS / 128), 256>>>(out, DMODEL);
}

// round 11
// speedup vs baseline: 2.5001x; 1.5902x over previous
#include <cuda_runtime.h>
#include <cuda_bf16.h>
#include <cstdint>

// B=2, S=2048, D_IN=2048, D_OUT=2048, H=32 heads, G=8 kv groups, R=4, D=64
#define SEQ    2048
#define DMODEL 2048
#define NHEAD  32
#define NGRP   8
#define HDIM   64
#define KDIM   2048

#define OUT_ELEMS  (2ull * SEQ * DMODEL)          // 8388608
#define KV_ELEMS   (2ull * NGRP * SEQ * HDIM)     // 2097152
#define MROWS      (2 * SEQ)                      // 4096

// ---------------- device-global scratch (allocation-free rule) --------------
__device__ __nv_bfloat16 g_xhi[(size_t)MROWS * DMODEL];
__device__ __nv_bfloat16 g_xlo[(size_t)MROWS * DMODEL];
__device__ __nv_bfloat16 g_whi[(size_t)DMODEL * DMODEL];
__device__ __nv_bfloat16 g_wlo[(size_t)DMODEL * DMODEL];
__device__ __nv_bfloat16 g_qhi[(size_t)MROWS * DMODEL];   // Q proj bf16 hi
__device__ __nv_bfloat16 g_qlo[(size_t)MROWS * DMODEL];
__device__ __nv_bfloat16 g_khi[KV_ELEMS];                 // K cache [bg][s][d]
__device__ __nv_bfloat16 g_klo[KV_ELEMS];
__device__ __nv_bfloat16 g_vthi[KV_ELEMS];                // V cache transposed [bg][d][s]
__device__ __nv_bfloat16 g_vtlo[KV_ELEMS];
__device__ __nv_bfloat16 g_chi[(size_t)MROWS * DMODEL];   // ctx bf16 hi
__device__ __nv_bfloat16 g_clo[(size_t)MROWS * DMODEL];

// ---------------- helpers ---------------------------------------------------
__device__ __forceinline__ void split2(float x, float y, uint32_t& hi, uint32_t& lo) {
    __nv_bfloat16 hx = __float2bfloat16(x), hy = __float2bfloat16(y);
    __nv_bfloat16 lx = __float2bfloat16(x - __bfloat162float(hx));
    __nv_bfloat16 ly = __float2bfloat16(y - __bfloat162float(hy));
    __nv_bfloat162 h{hx, hy}, l{lx, ly};
    hi = *(uint32_t*)&h;
    lo = *(uint32_t*)&l;
}

__device__ __forceinline__ void mma16816(float* d, const uint32_t* a, const uint32_t* b) {
    asm volatile(
        "mma.sync.aligned.m16n8k16.row.col.f32.bf16.bf16.f32 "
        "{%0,%1,%2,%3}, {%4,%5,%6,%7}, {%8,%9}, {%0,%1,%2,%3};\n"
        : "+f"(d[0]), "+f"(d[1]), "+f"(d[2]), "+f"(d[3])
        : "r"(a[0]), "r"(a[1]), "r"(a[2]), "r"(a[3]), "r"(b[0]), "r"(b[1]));
}

// ---------------------------------------------------------------------------
// fp32 -> bf16 hi/lo split. DST: 0 = x buffers, 1 = w buffers.
// ---------------------------------------------------------------------------
template<int DST>
__global__ void __launch_bounds__(256) cvt_split(const float* __restrict__ srcp, int n4) {
    const float4* s = (const float4*)srcp;
    uint2* hp = (uint2*)(DST == 0 ? g_xhi : g_whi);
    uint2* lp = (uint2*)(DST == 0 ? g_xlo : g_wlo);
    for (int i = blockIdx.x * blockDim.x + threadIdx.x; i < n4;
         i += gridDim.x * blockDim.x) {
        float4 v = s[i];
        uint32_t h0, l0, h1, l1;
        split2(v.x, v.y, h0, l0);
        split2(v.z, v.w, h1, l1);
        hp[i] = uint2{h0, h1};
        lp[i] = uint2{l0, l1};
    }
}

// ---------------------------------------------------------------------------
// Split-bf16 mma.sync GEMM: C[M,N] = A @ W^T  (Ahi*Whi + Alo*Whi + Ahi*Wlo)
// CTA 128x128, 8 warps (32x64 each), BK=16, 2-stage 48KB smem double buffer.
// AB: 0 = A from g_xhi/g_xlo, 1 = A from g_chi/g_clo.
// OM: 0 = fp32 C row-major.   2 = Q: bf16 hi/lo row-major (g_qhi/g_qlo).
//     1 = K: fp32 kv-cache + bf16 hi/lo [bg][s][d].
//     3 = V: fp32 kv-cache + bf16 hi/lo TRANSPOSED [bg][d][s].
// ---------------------------------------------------------------------------
#define LDK   24
#define TILE_H (128 * LDK)
#define STAGE_H (4 * TILE_H)

template<int AB, int OM>
__global__ void __launch_bounds__(256) gemm_mma(float* __restrict__ C, int N) {
    __shared__ __nv_bfloat16 smbuf[2 * STAGE_H];   // 49152 bytes

    const int tid  = threadIdx.x;
    const int wid  = tid >> 5;
    const int lane = tid & 31;
    const int g    = lane >> 2;
    const int tq   = lane & 3;
    const int m0 = blockIdx.y * 128;
    const int n0 = blockIdx.x * 128;
    const int m_off = (wid & 3) * 32;
    const int n_off = (wid >> 2) * 64;

    const __nv_bfloat16* __restrict__ Ahi = AB ? g_chi : g_xhi;
    const __nv_bfloat16* __restrict__ Alo = AB ? g_clo : g_xlo;

    const int r_cp = tid >> 1;
    const int h_cp = (tid & 1) * 8;
    const size_t gA = (size_t)(m0 + r_cp) * KDIM + h_cp;
    const size_t gW = (size_t)(n0 + r_cp) * KDIM + h_cp;
    const int s_cp = r_cp * LDK + h_cp;

    float acc[2][8][4] = {};
    uint4 stg[4];

    stg[0] = *(const uint4*)&Ahi  [gA];
    stg[1] = *(const uint4*)&Alo  [gA];
    stg[2] = *(const uint4*)&g_whi[gW];
    stg[3] = *(const uint4*)&g_wlo[gW];
    {
        __nv_bfloat16* st0 = smbuf;
        *(uint4*)&st0[0 * TILE_H + s_cp] = stg[0];
        *(uint4*)&st0[1 * TILE_H + s_cp] = stg[1];
        *(uint4*)&st0[2 * TILE_H + s_cp] = stg[2];
        *(uint4*)&st0[3 * TILE_H + s_cp] = stg[3];
    }

    const int NCH = KDIM / 16;
    for (int c = 0; c < NCH; c++) {
        __syncthreads();

        if (c + 1 < NCH) {
            const size_t ko = (size_t)(c + 1) * 16;
            stg[0] = *(const uint4*)&Ahi  [gA + ko];
            stg[1] = *(const uint4*)&Alo  [gA + ko];
            stg[2] = *(const uint4*)&g_whi[gW + ko];
            stg[3] = *(const uint4*)&g_wlo[gW + ko];
        }

        const __nv_bfloat16* Sb  = smbuf + (c & 1) * STAGE_H;
        const __nv_bfloat16* Sah = Sb;
        const __nv_bfloat16* Sal = Sb + TILE_H;
        const __nv_bfloat16* Swh = Sb + 2 * TILE_H;
        const __nv_bfloat16* Swl = Sb + 3 * TILE_H;
        const int kb = 2 * tq;

        uint32_t ah[2][4], al[2][4], wh[8][2], wl[8][2];
        #pragma unroll
        for (int mi = 0; mi < 2; mi++) {
            const int r = m_off + mi * 16 + g;
            ah[mi][0] = *(const uint32_t*)&Sah[r * LDK + kb];
            ah[mi][1] = *(const uint32_t*)&Sah[(r + 8) * LDK + kb];
            ah[mi][2] = *(const uint32_t*)&Sah[r * LDK + kb + 8];
            ah[mi][3] = *(const uint32_t*)&Sah[(r + 8) * LDK + kb + 8];
            al[mi][0] = *(const uint32_t*)&Sal[r * LDK + kb];
            al[mi][1] = *(const uint32_t*)&Sal[(r + 8) * LDK + kb];
            al[mi][2] = *(const uint32_t*)&Sal[r * LDK + kb + 8];
            al[mi][3] = *(const uint32_t*)&Sal[(r + 8) * LDK + kb + 8];
        }
        #pragma unroll
        for (int ni = 0; ni < 8; ni++) {
            const int r = n_off + ni * 8 + g;
            wh[ni][0] = *(const uint32_t*)&Swh[r * LDK + kb];
            wh[ni][1] = *(const uint32_t*)&Swh[r * LDK + kb + 8];
            wl[ni][0] = *(const uint32_t*)&Swl[r * LDK + kb];
            wl[ni][1] = *(const uint32_t*)&Swl[r * LDK + kb + 8];
        }
        #pragma unroll
        for (int mi = 0; mi < 2; mi++)
            #pragma unroll
            for (int ni = 0; ni < 8; ni++)
                mma16816(acc[mi][ni], ah[mi], wh[ni]);
        #pragma unroll
        for (int mi = 0; mi < 2; mi++)
            #pragma unroll
            for (int ni = 0; ni < 8; ni++)
                mma16816(acc[mi][ni], al[mi], wh[ni]);
        #pragma unroll
        for (int mi = 0; mi < 2; mi++)
            #pragma unroll
            for (int ni = 0; ni < 8; ni++)
                mma16816(acc[mi][ni], ah[mi], wl[ni]);

        if (c + 1 < NCH) {
            __nv_bfloat16* st = smbuf + ((c + 1) & 1) * STAGE_H;
            *(uint4*)&st[0 * TILE_H + s_cp] = stg[0];
            *(uint4*)&st[1 * TILE_H + s_cp] = stg[1];
            *(uint4*)&st[2 * TILE_H + s_cp] = stg[2];
            *(uint4*)&st[3 * TILE_H + s_cp] = stg[3];
        }
    }

    // ---- epilogue ----
    #pragma unroll
    for (int mi = 0; mi < 2; mi++) {
        #pragma unroll
        for (int ni = 0; ni < 8; ni++) {
            const int nloc = n_off + ni * 8 + 2 * tq;
            #pragma unroll
            for (int h2 = 0; h2 < 2; h2++) {
                const int m = m0 + m_off + mi * 16 + g + h2 * 8;
                const float vx = acc[mi][ni][h2 * 2], vy = acc[mi][ni][h2 * 2 + 1];
                const int n = n0 + nloc;
                if (OM == 0) {
                    *(float2*)&C[(size_t)m * N + n] = make_float2(vx, vy);
                } else if (OM == 2) {
                    uint32_t hi, lo;
                    split2(vx, vy, hi, lo);
                    *(uint32_t*)&g_qhi[(size_t)m * DMODEL + n] = hi;
                    *(uint32_t*)&g_qlo[(size_t)m * DMODEL + n] = lo;
                } else {
                    const int bb = m >> 11, s = m & 2047;
                    const int gg = n >> 6, d = n & 63;
                    const size_t bg = (size_t)(bb * NGRP + gg);
                    *(float2*)&C[(bg * SEQ + s) * HDIM + d] = make_float2(vx, vy);
                    uint32_t hi, lo;
                    split2(vx, vy, hi, lo);
                    if (OM == 1) {
                        *(uint32_t*)&g_khi[(bg * SEQ + s) * HDIM + d] = hi;
                        *(uint32_t*)&g_klo[(bg * SEQ + s) * HDIM + d] = lo;
                    } else {  // OM == 3: transposed bf16 V cache
                        __nv_bfloat162 h2v = *(__nv_bfloat162*)&hi;
                        __nv_bfloat162 l2v = *(__nv_bfloat162*)&lo;
                        g_vthi[(bg * HDIM + d    ) * SEQ + s] = h2v.x;
                        g_vthi[(bg * HDIM + d + 1) * SEQ + s] = h2v.y;
                        g_vtlo[(bg * HDIM + d    ) * SEQ + s] = l2v.x;
                        g_vtlo[(bg * HDIM + d + 1) * SEQ + s] = l2v.y;
                    }
                }
            }
        }
    }
}

// ---------------------------------------------------------------------------
// mma.sync flash attention (causal), split-bf16, fp32 accumulate.
// CTA = (qt: 128 q rows, b, h). 4 warps, warp owns 32 rows. 64-key tiles.
// Dynamic smem 73728 B: Qhi/Qlo[128][72], Khi/Klo[64][72], Vthi/Vtlo[64][72].
// ---------------------------------------------------------------------------
#define ATT_SMEM 73728

__global__ void __launch_bounds__(128) attn_mma() {
    extern __shared__ __nv_bfloat16 sm[];
    __nv_bfloat16* Qh = sm;            // 128*72 = 9216
    __nv_bfloat16* Ql = Qh + 9216;
    __nv_bfloat16* Kh = Ql + 9216;     // 64*72 = 4608
    __nv_bfloat16* Kl = Kh + 4608;
    __nv_bfloat16* Vh = Kl + 4608;     // transposed [d][k]
    __nv_bfloat16* Vl = Vh + 4608;

    const int tid  = threadIdx.x;
    const int wid  = tid >> 5;
    const int lane = tid & 31;
    const int g    = lane >> 2;
    const int tq   = lane & 3;
    const int qt = blockIdx.x;
    const int b  = blockIdx.y >> 5;
    const int h  = blockIdx.y & 31;
    const int grp = h >> 2;
    const int q0 = qt * 128;
    const int m_off = wid * 32;
    const size_t bg = (size_t)(b * NGRP + grp);

    // Q tile (hi/lo)
    {
        const size_t qb = ((size_t)(b * SEQ + q0)) * DMODEL + h * HDIM;
        for (int i = tid; i < 1024; i += 128) {
            int r = i >> 3, c = (i & 7) * 8;
            *(uint4*)&Qh[r * 72 + c] = *(const uint4*)&g_qhi[qb + (size_t)r * DMODEL + c];
            *(uint4*)&Ql[r * 72 + c] = *(const uint4*)&g_qlo[qb + (size_t)r * DMODEL + c];
        }
    }

    float oacc[2][8][4] = {};
    float mrow[2][2], lrow[2][2];
    #pragma unroll
    for (int mi = 0; mi < 2; mi++) {
        mrow[mi][0] = mrow[mi][1] = -1e30f;
        lrow[mi][0] = lrow[mi][1] = 0.f;
    }

    const __nv_bfloat16* Kh_g = g_khi  + bg * SEQ * HDIM;
    const __nv_bfloat16* Kl_g = g_klo  + bg * SEQ * HDIM;
    const __nv_bfloat16* Vh_g = g_vthi + bg * HDIM * SEQ;
    const __nv_bfloat16* Vl_g = g_vtlo + bg * HDIM * SEQ;

    const int njt = 2 * qt + 2;
    for (int jt = 0; jt < njt; jt++) {
        const int j0 = jt * 64;
        __syncthreads();   // prior tile reads done
        for (int i = tid; i < 512; i += 128) {
            int r = i >> 3, c = (i & 7) * 8;
            *(uint4*)&Kh[r * 72 + c] = *(const uint4*)&Kh_g[(size_t)(j0 + r) * HDIM + c];
            *(uint4*)&Kl[r * 72 + c] = *(const uint4*)&Kl_g[(size_t)(j0 + r) * HDIM + c];
            *(uint4*)&Vh[r * 72 + c] = *(const uint4*)&Vh_g[(size_t)r * SEQ + j0 + c];
            *(uint4*)&Vl[r * 72 + c] = *(const uint4*)&Vl_g[(size_t)r * SEQ + j0 + c];
        }
        __syncthreads();

        if (j0 > q0 + m_off + 31) continue;   // tile fully masked for this warp

        // ---- S = Q K^T (3-term split) ----
        float sacc[2][8][4] = {};
        #pragma unroll
        for (int ks = 0; ks < 4; ks++) {
            const int kb = 16 * ks + 2 * tq;
            uint32_t ah[2][4], al[2][4];
            #pragma unroll
            for (int mi = 0; mi < 2; mi++) {
                const int r = m_off + mi * 16 + g;
                ah[mi][0] = *(const uint32_t*)&Qh[r * 72 + kb];
                ah[mi][1] = *(const uint32_t*)&Qh[(r + 8) * 72 + kb];
                ah[mi][2] = *(const uint32_t*)&Qh[r * 72 + kb + 8];
                ah[mi][3] = *(const uint32_t*)&Qh[(r + 8) * 72 + kb + 8];
                al[mi][0] = *(const uint32_t*)&Ql[r * 72 + kb];
                al[mi][1] = *(const uint32_t*)&Ql[(r + 8) * 72 + kb];
                al[mi][2] = *(const uint32_t*)&Ql[r * 72 + kb + 8];
                al[mi][3] = *(const uint32_t*)&Ql[(r + 8) * 72 + kb + 8];
            }
            #pragma unroll
            for (int nf = 0; nf < 8; nf++) {
                const int kr = nf * 8 + g;
                uint32_t bhf[2], blf[2];
                bhf[0] = *(const uint32_t*)&Kh[kr * 72 + kb];
                bhf[1] = *(const uint32_t*)&Kh[kr * 72 + kb + 8];
                blf[0] = *(const uint32_t*)&Kl[kr * 72 + kb];
                blf[1] = *(const uint32_t*)&Kl[kr * 72 + kb + 8];
                #pragma unroll
                for (int mi = 0; mi < 2; mi++) {
                    mma16816(sacc[mi][nf], ah[mi], bhf);
                    mma16816(sacc[mi][nf], al[mi], bhf);
                    mma16816(sacc[mi][nf], ah[mi], blf);
                }
            }
        }

        // scale + causal mask
        #pragma unroll
        for (int mi = 0; mi < 2; mi++)
            #pragma unroll
            for (int nf = 0; nf < 8; nf++)
                #pragma unroll
                for (int e = 0; e < 4; e++)
                    sacc[mi][nf][e] *= 0.125f;
        if (j0 + 63 > q0 + m_off) {
            #pragma unroll
            for (int mi = 0; mi < 2; mi++)
                #pragma unroll
                for (int nf = 0; nf < 8; nf++)
                    #pragma unroll
                    for (int e = 0; e < 4; e++) {
                        const int m = q0 + m_off + mi * 16 + g + ((e >> 1) << 3);
                        const int n = j0 + nf * 8 + 2 * tq + (e & 1);
                        if (n > m) sacc[mi][nf][e] = -1e30f;
                    }
        }

        // ---- online softmax (per warp, quad shuffles) ----
        #pragma unroll
        for (int mi = 0; mi < 2; mi++) {
            float mx0 = -1e30f, mx1 = -1e30f;
            #pragma unroll
            for (int nf = 0; nf < 8; nf++) {
                mx0 = fmaxf(mx0, fmaxf(sacc[mi][nf][0], sacc[mi][nf][1]));
                mx1 = fmaxf(mx1, fmaxf(sacc[mi][nf][2], sacc[mi][nf][3]));
            }
            mx0 = fmaxf(mx0, __shfl_xor_sync(0xffffffffu, mx0, 1));
            mx0 = fmaxf(mx0, __shfl_xor_sync(0xffffffffu, mx0, 2));
            mx1 = fmaxf(mx1, __shfl_xor_sync(0xffffffffu, mx1, 1));
            mx1 = fmaxf(mx1, __shfl_xor_sync(0xffffffffu, mx1, 2));
            const float mn0 = fmaxf(mrow[mi][0], mx0);
            const float mn1 = fmaxf(mrow[mi][1], mx1);
            const float f0 = __expf(mrow[mi][0] - mn0);
            const float f1 = __expf(mrow[mi][1] - mn1);
            mrow[mi][0] = mn0;
            mrow[mi][1] = mn1;
            float s0 = 0.f, s1 = 0.f;
            #pragma unroll
            for (int nf = 0; nf < 8; nf++) {
                sacc[mi][nf][0] = __expf(sacc[mi][nf][0] - mn0); s0 += sacc[mi][nf][0];
                sacc[mi][nf][1] = __expf(sacc[mi][nf][1] - mn0); s0 += sacc[mi][nf][1];
                sacc[mi][nf][2] = __expf(sacc[mi][nf][2] - mn1); s1 += sacc[mi][nf][2];
                sacc[mi][nf][3] = __expf(sacc[mi][nf][3] - mn1); s1 += sacc[mi][nf][3];
            }
            s0 += __shfl_xor_sync(0xffffffffu, s0, 1);
            s0 += __shfl_xor_sync(0xffffffffu, s0, 2);
            s1 += __shfl_xor_sync(0xffffffffu, s1, 1);
            s1 += __shfl_xor_sync(0xffffffffu, s1, 2);
            lrow[mi][0] = lrow[mi][0] * f0 + s0;
            lrow[mi][1] = lrow[mi][1] * f1 + s1;
            #pragma unroll
            for (int nf = 0; nf < 8; nf++) {
                oacc[mi][nf][0] *= f0;
                oacc[mi][nf][1] *= f0;
                oacc[mi][nf][2] *= f1;
                oacc[mi][nf][3] *= f1;
            }
        }

        // ---- ctx += P V (3-term split, P from registers) ----
        #pragma unroll
        for (int ks = 0; ks < 4; ks++) {
            uint32_t ph[2][4], pl[2][4];
            #pragma unroll
            for (int mi = 0; mi < 2; mi++) {
                split2(sacc[mi][2 * ks][0],     sacc[mi][2 * ks][1],     ph[mi][0], pl[mi][0]);
                split2(sacc[mi][2 * ks][2],     sacc[mi][2 * ks][3],     ph[mi][1], pl[mi][1]);
                split2(sacc[mi][2 * ks + 1][0], sacc[mi][2 * ks + 1][1], ph[mi][2], pl[mi][2]);
                split2(sacc[mi][2 * ks + 1][2], sacc[mi][2 * ks + 1][3], ph[mi][3], pl[mi][3]);
            }
            const int kb = 16 * ks + 2 * tq;
            #pragma unroll
            for (int nf = 0; nf < 8; nf++) {
                const int dr = nf * 8 + g;
                uint32_t bhf[2], blf[2];
                bhf[0] = *(const uint32_t*)&Vh[dr * 72 + kb];
                bhf[1] = *(const uint32_t*)&Vh[dr * 72 + kb + 8];
                blf[0] = *(const uint32_t*)&Vl[dr * 72 + kb];
                blf[1] = *(const uint32_t*)&Vl[dr * 72 + kb + 8];
                #pragma unroll
                for (int mi = 0; mi < 2; mi++) {
                    mma16816(oacc[mi][nf], ph[mi], bhf);
                    mma16816(oacc[mi][nf], pl[mi], bhf);
                    mma16816(oacc[mi][nf], ph[mi], blf);
                }
            }
        }
    }

    // ---- epilogue: normalize, split, store ctx bf16 hi/lo ----
    #pragma unroll
    for (int mi = 0; mi < 2; mi++) {
        const float i0 = 1.f / lrow[mi][0];
        const float i1 = 1.f / lrow[mi][1];
        const int r0 = q0 + m_off + mi * 16 + g;
        #pragma unroll
        for (int nf = 0; nf < 8; nf++) {
            const int col = h * HDIM + nf * 8 + 2 * tq;
            uint32_t hi, lo;
            split2(oacc[mi][nf][0] * i0, oacc[mi][nf][1] * i0, hi, lo);
            *(uint32_t*)&g_chi[(size_t)(b * SEQ + r0) * DMODEL + col] = hi;
            *(uint32_t*)&g_clo[(size_t)(b * SEQ + r0) * DMODEL + col] = lo;
            split2(oacc[mi][nf][2] * i1, oacc[mi][nf][3] * i1, hi, lo);
            *(uint32_t*)&g_chi[(size_t)(b * SEQ + r0 + 8) * DMODEL + col] = hi;
            *(uint32_t*)&g_clo[(size_t)(b * SEQ + r0 + 8) * DMODEL + col] = lo;
        }
    }
}

// ---------------------------------------------------------------------------
// Launch
// ---------------------------------------------------------------------------
extern "C" void kernel_launch(void* const* d_in, const int* in_sizes, int n_in,
                              void* d_out, int out_size) {
    const float* x  = (const float*)d_in[0];
    const float* Wq = (const float*)d_in[1];
    const float* Wk = (const float*)d_in[2];
    const float* Wv = (const float*)d_in[3];
    const float* Wo = (const float*)d_in[4];

    float* out  = (float*)d_out;
    float* keys = out + OUT_ELEMS;             // [b,g,s,d]
    float* vals = keys + KV_ELEMS;             // [b,g,s,d]

    cudaFuncSetAttribute((const void*)attn_mma,
                         cudaFuncAttributeMaxDynamicSharedMemorySize, ATT_SMEM);

    // x -> bf16 hi/lo
    cvt_split<0><<<2048, 256>>>(x, (int)(MROWS * DMODEL / 4));
    // Q = x @ Wq^T -> qhi/qlo (bf16)
    cvt_split<1><<<2048, 256>>>(Wq, DMODEL * DMODEL / 4);
    gemm_mma<0, 2><<<dim3(DMODEL / 128, MROWS / 128), 256>>>(nullptr, DMODEL);
    // K = x @ Wk^T -> keys fp32 + khi/klo bf16
    cvt_split<1><<<2048, 256>>>(Wk, NGRP * HDIM * DMODEL / 4);
    gemm_mma<0, 1><<<dim3(NGRP * HDIM / 128, MROWS / 128), 256>>>(keys, NGRP * HDIM);
    // V = x @ Wv^T -> vals fp32 + vthi/vtlo bf16 (transposed)
    cvt_split<1><<<2048, 256>>>(Wv, NGRP * HDIM * DMODEL / 4);
    gemm_mma<0, 3><<<dim3(NGRP * HDIM / 128, MROWS / 128), 256>>>(vals, NGRP * HDIM);
    // Attention -> chi/clo
    attn_mma<<<dim3(SEQ / 128, 2 * NHEAD), 128, ATT_SMEM>>>();
    // out = ctx @ Wo^T
    cvt_split<1><<<2048, 256>>>(Wo, DMODEL * DMODEL / 4);
    gemm_mma<1, 0><<<dim3(DMODEL / 128, MROWS / 128), 256>>>(out, DMODEL);
}

// round 14
// speedup vs baseline: 3.4193x; 1.3677x over previous
#include <cuda_runtime.h>
#include <cuda_fp16.h>
#include <cstdint>

// B=2, S=2048, D_IN=2048, D_OUT=2048, H=32 heads, G=8 kv groups, R=4, D=64
#define SEQ    2048
#define DMODEL 2048
#define NHEAD  32
#define NGRP   8
#define HDIM   64
#define KDIM   2048

#define OUT_ELEMS  (2ull * SEQ * DMODEL)          // 8388608
#define KV_ELEMS   (2ull * NGRP * SEQ * HDIM)     // 2097152
#define MROWS      (2 * SEQ)                      // 4096

// ---------------- device-global scratch (allocation-free rule) --------------
__device__ __half g_xhi[(size_t)MROWS * DMODEL];
__device__ __half g_xlo[(size_t)MROWS * DMODEL];
__device__ __half g_whi[(size_t)DMODEL * DMODEL];
__device__ __half g_qhi[(size_t)MROWS * DMODEL];   // Q proj fp16 hi
__device__ __half g_qlo[(size_t)MROWS * DMODEL];
__device__ __half g_khi[KV_ELEMS];                 // K cache fp16 hi [bg][s][d]
__device__ __half g_vthi[KV_ELEMS];                // V cache fp16 hi transposed [bg][d][s]
__device__ __half g_chi[(size_t)MROWS * DMODEL];   // ctx fp16 hi
__device__ __half g_clo[(size_t)MROWS * DMODEL];

// ---------------- helpers ---------------------------------------------------
__device__ __forceinline__ void split2h(float x, float y, uint32_t& hi, uint32_t& lo) {
    __half hx = __float2half(x), hy = __float2half(y);
    __half lx = __float2half(x - __half2float(hx));
    __half ly = __float2half(y - __half2float(hy));
    __half2 h{hx, hy}, l{lx, ly};
    hi = *(uint32_t*)&h;
    lo = *(uint32_t*)&l;
}

__device__ __forceinline__ void mma16816(float* d, const uint32_t* a, const uint32_t* b) {
    asm volatile(
        "mma.sync.aligned.m16n8k16.row.col.f32.f16.f16.f32 "
        "{%0,%1,%2,%3}, {%4,%5,%6,%7}, {%8,%9}, {%0,%1,%2,%3};\n"
        : "+f"(d[0]), "+f"(d[1]), "+f"(d[2]), "+f"(d[3])
        : "r"(a[0]), "r"(a[1]), "r"(a[2]), "r"(a[3]), "r"(b[0]), "r"(b[1]));
}

// ---------------------------------------------------------------------------
// fp32 -> fp16 hi/lo split. DST 0: x (hi+lo). DST 1: W (hi only — lo unused).
// ---------------------------------------------------------------------------
template<int DST>
__global__ void __launch_bounds__(256) cvt_split(const float* __restrict__ srcp, int n4) {
    const float4* s = (const float4*)srcp;
    uint2* hp = (uint2*)(DST == 0 ? g_xhi : g_whi);
    uint2* lp = (uint2*)g_xlo;
    for (int i = blockIdx.x * blockDim.x + threadIdx.x; i < n4;
         i += gridDim.x * blockDim.x) {
        float4 v = s[i];
        uint32_t h0, l0, h1, l1;
        split2h(v.x, v.y, h0, l0);
        split2h(v.z, v.w, h1, l1);
        hp[i] = uint2{h0, h1};
        if (DST == 0) lp[i] = uint2{l0, l1};
    }
}

// ---------------------------------------------------------------------------
// Split-fp16 mma.sync GEMM: C[M,N] = A @ W^T  (Ahi*Whi + Alo*Whi)
// CTA 128x128, 8 warps (32x64 each), BK=16, 2-stage smem double buffer
// (3 tiles/stage = 36 KB static).
// AB: 0 = A from g_xhi/g_xlo, 1 = A from g_chi/g_clo.
// OM: 0 = fp32 C row-major.   2 = Q: fp16 hi/lo row-major (g_qhi/g_qlo).
//     1 = K: fp32 kv-cache + fp16 hi [bg][s][d].
//     3 = V: fp32 kv-cache + fp16 hi TRANSPOSED [bg][d][s].
// ---------------------------------------------------------------------------
#define LDK   24
#define TILE_H (128 * LDK)
#define STAGE_H (3 * TILE_H)

template<int AB, int OM>
__global__ void __launch_bounds__(256) gemm_mma(float* __restrict__ C, int N) {
    __shared__ __half smbuf[2 * STAGE_H];   // 36864 bytes

    const int tid  = threadIdx.x;
    const int wid  = tid >> 5;
    const int lane = tid & 31;
    const int g    = lane >> 2;
    const int tq   = lane & 3;
    const int m0 = blockIdx.y * 128;
    const int n0 = blockIdx.x * 128;
    const int m_off = (wid & 3) * 32;
    const int n_off = (wid >> 2) * 64;

    const __half* __restrict__ Ahi = AB ? g_chi : g_xhi;
    const __half* __restrict__ Alo = AB ? g_clo : g_xlo;

    const int r_cp = tid >> 1;
    const int h_cp = (tid & 1) * 8;
    const size_t gA = (size_t)(m0 + r_cp) * KDIM + h_cp;
    const size_t gW = (size_t)(n0 + r_cp) * KDIM + h_cp;
    const int s_cp = r_cp * LDK + h_cp;

    float acc[2][8][4] = {};
    uint4 stg[3];

    stg[0] = *(const uint4*)&Ahi  [gA];
    stg[1] = *(const uint4*)&Alo  [gA];
    stg[2] = *(const uint4*)&g_whi[gW];
    {
        __half* st0 = smbuf;
        *(uint4*)&st0[0 * TILE_H + s_cp] = stg[0];
        *(uint4*)&st0[1 * TILE_H + s_cp] = stg[1];
        *(uint4*)&st0[2 * TILE_H + s_cp] = stg[2];
    }

    const int NCH = KDIM / 16;
    for (int c = 0; c < NCH; c++) {
        __syncthreads();

        if (c + 1 < NCH) {
            const size_t ko = (size_t)(c + 1) * 16;
            stg[0] = *(const uint4*)&Ahi  [gA + ko];
            stg[1] = *(const uint4*)&Alo  [gA + ko];
            stg[2] = *(const uint4*)&g_whi[gW + ko];
        }

        const __half* Sb  = smbuf + (c & 1) * STAGE_H;
        const __half* Sah = Sb;
        const __half* Sal = Sb + TILE_H;
        const __half* Swh = Sb + 2 * TILE_H;
        const int kb = 2 * tq;

        uint32_t ah[2][4], al[2][4], wh[8][2];
        #pragma unroll
        for (int mi = 0; mi < 2; mi++) {
            const int r = m_off + mi * 16 + g;
            ah[mi][0] = *(const uint32_t*)&Sah[r * LDK + kb];
            ah[mi][1] = *(const uint32_t*)&Sah[(r + 8) * LDK + kb];
            ah[mi][2] = *(const uint32_t*)&Sah[r * LDK + kb + 8];
            ah[mi][3] = *(const uint32_t*)&Sah[(r + 8) * LDK + kb + 8];
            al[mi][0] = *(const uint32_t*)&Sal[r * LDK + kb];
            al[mi][1] = *(const uint32_t*)&Sal[(r + 8) * LDK + kb];
            al[mi][2] = *(const uint32_t*)&Sal[r * LDK + kb + 8];
            al[mi][3] = *(const uint32_t*)&Sal[(r + 8) * LDK + kb + 8];
        }
        #pragma unroll
        for (int ni = 0; ni < 8; ni++) {
            const int r = n_off + ni * 8 + g;
            wh[ni][0] = *(const uint32_t*)&Swh[r * LDK + kb];
            wh[ni][1] = *(const uint32_t*)&Swh[r * LDK + kb + 8];
        }
        #pragma unroll
        for (int mi = 0; mi < 2; mi++)
            #pragma unroll
            for (int ni = 0; ni < 8; ni++)
                mma16816(acc[mi][ni], ah[mi], wh[ni]);
        #pragma unroll
        for (int mi = 0; mi < 2; mi++)
            #pragma unroll
            for (int ni = 0; ni < 8; ni++)
                mma16816(acc[mi][ni], al[mi], wh[ni]);

        if (c + 1 < NCH) {
            __half* st = smbuf + ((c + 1) & 1) * STAGE_H;
            *(uint4*)&st[0 * TILE_H + s_cp] = stg[0];
            *(uint4*)&st[1 * TILE_H + s_cp] = stg[1];
            *(uint4*)&st[2 * TILE_H + s_cp] = stg[2];
        }
    }

    // ---- epilogue ----
    #pragma unroll
    for (int mi = 0; mi < 2; mi++) {
        #pragma unroll
        for (int ni = 0; ni < 8; ni++) {
            const int nloc = n_off + ni * 8 + 2 * tq;
            #pragma unroll
            for (int h2 = 0; h2 < 2; h2++) {
                const int m = m0 + m_off + mi * 16 + g + h2 * 8;
                const float vx = acc[mi][ni][h2 * 2], vy = acc[mi][ni][h2 * 2 + 1];
                const int n = n0 + nloc;
                if (OM == 0) {
                    *(float2*)&C[(size_t)m * N + n] = make_float2(vx, vy);
                } else if (OM == 2) {
                    uint32_t hi, lo;
                    split2h(vx, vy, hi, lo);
                    *(uint32_t*)&g_qhi[(size_t)m * DMODEL + n] = hi;
                    *(uint32_t*)&g_qlo[(size_t)m * DMODEL + n] = lo;
                } else {
                    const int bb = m >> 11, s = m & 2047;
                    const int gg = n >> 6, d = n & 63;
                    const size_t bg = (size_t)(bb * NGRP + gg);
                    *(float2*)&C[(bg * SEQ + s) * HDIM + d] = make_float2(vx, vy);
                    __half hx = __float2half(vx), hy = __float2half(vy);
                    if (OM == 1) {
                        __half2 hh{hx, hy};
                        *(__half2*)&g_khi[(bg * SEQ + s) * HDIM + d] = hh;
                    } else {  // OM == 3: transposed fp16 V cache
                        g_vthi[(bg * HDIM + d    ) * SEQ + s] = hx;
                        g_vthi[(bg * HDIM + d + 1) * SEQ + s] = hy;
                    }
                }
            }
        }
    }
}

// ---------------------------------------------------------------------------
// mma.sync flash attention (causal), split-fp16 (2-term), fp32 accumulate.
// CTA = (qt: 128 q rows, b, h). 4 warps, warp owns 32 rows. 64-key tiles.
// Dynamic smem 55296 B: Qhi/Qlo[128][72], Khi[64][72], Vthi[64][72].
// ---------------------------------------------------------------------------
#define ATT_SMEM 55296

__global__ void __launch_bounds__(128) attn_mma() {
    extern __shared__ __half sm[];
    __half* Qh = sm;            // 128*72 = 9216
    __half* Ql = Qh + 9216;
    __half* Kh = Ql + 9216;     // 64*72 = 4608
    __half* Vh = Kh + 4608;     // transposed [d][k]

    const int tid  = threadIdx.x;
    const int wid  = tid >> 5;
    const int lane = tid & 31;
    const int g    = lane >> 2;
    const int tq   = lane & 3;
    const int qt = blockIdx.x;
    const int b  = blockIdx.y >> 5;
    const int h  = blockIdx.y & 31;
    const int grp = h >> 2;
    const int q0 = qt * 128;
    const int m_off = wid * 32;
    const size_t bg = (size_t)(b * NGRP + grp);

    {
        const size_t qb = ((size_t)(b * SEQ + q0)) * DMODEL + h * HDIM;
        for (int i = tid; i < 1024; i += 128) {
            int r = i >> 3, c = (i & 7) * 8;
            *(uint4*)&Qh[r * 72 + c] = *(const uint4*)&g_qhi[qb + (size_t)r * DMODEL + c];
            *(uint4*)&Ql[r * 72 + c] = *(const uint4*)&g_qlo[qb + (size_t)r * DMODEL + c];
        }
    }

    float oacc[2][8][4] = {};
    float mrow[2][2], lrow[2][2];
    #pragma unroll
    for (int mi = 0; mi < 2; mi++) {
        mrow[mi][0] = mrow[mi][1] = -1e30f;
        lrow[mi][0] = lrow[mi][1] = 0.f;
    }

    const __half* Kh_g = g_khi  + bg * SEQ * HDIM;
    const __half* Vh_g = g_vthi + bg * HDIM * SEQ;

    const int njt = 2 * qt + 2;
    for (int jt = 0; jt < njt; jt++) {
        const int j0 = jt * 64;
        __syncthreads();
        for (int i = tid; i < 512; i += 128) {
            int r = i >> 3, c = (i & 7) * 8;
            *(uint4*)&Kh[r * 72 + c] = *(const uint4*)&Kh_g[(size_t)(j0 + r) * HDIM + c];
            *(uint4*)&Vh[r * 72 + c] = *(const uint4*)&Vh_g[(size_t)r * SEQ + j0 + c];
        }
        __syncthreads();

        if (j0 > q0 + m_off + 31) continue;

        // ---- S = Q K^T (2-term split) ----
        float sacc[2][8][4] = {};
        #pragma unroll
        for (int ks = 0; ks < 4; ks++) {
            const int kb = 16 * ks + 2 * tq;
            uint32_t ah[2][4], al[2][4];
            #pragma unroll
            for (int mi = 0; mi < 2; mi++) {
                const int r = m_off + mi * 16 + g;
                ah[mi][0] = *(const uint32_t*)&Qh[r * 72 + kb];
                ah[mi][1] = *(const uint32_t*)&Qh[(r + 8) * 72 + kb];
                ah[mi][2] = *(const uint32_t*)&Qh[r * 72 + kb + 8];
                ah[mi][3] = *(const uint32_t*)&Qh[(r + 8) * 72 + kb + 8];
                al[mi][0] = *(const uint32_t*)&Ql[r * 72 + kb];
                al[mi][1] = *(const uint32_t*)&Ql[(r + 8) * 72 + kb];
                al[mi][2] = *(const uint32_t*)&Ql[r * 72 + kb + 8];
                al[mi][3] = *(const uint32_t*)&Ql[(r + 8) * 72 + kb + 8];
            }
            #pragma unroll
            for (int nf = 0; nf < 8; nf++) {
                const int kr = nf * 8 + g;
                uint32_t bhf[2];
                bhf[0] = *(const uint32_t*)&Kh[kr * 72 + kb];
                bhf[1] = *(const uint32_t*)&Kh[kr * 72 + kb + 8];
                #pragma unroll
                for (int mi = 0; mi < 2; mi++) {
                    mma16816(sacc[mi][nf], ah[mi], bhf);
                    mma16816(sacc[mi][nf], al[mi], bhf);
                }
            }
        }

        // scale + causal mask
        #pragma unroll
        for (int mi = 0; mi < 2; mi++)
            #pragma unroll
            for (int nf = 0; nf < 8; nf++)
                #pragma unroll
                for (int e = 0; e < 4; e++)
                    sacc[mi][nf][e] *= 0.125f;
        if (j0 + 63 > q0 + m_off) {
            #pragma unroll
            for (int mi = 0; mi < 2; mi++)
                #pragma unroll
                for (int nf = 0; nf < 8; nf++)
                    #pragma unroll
                    for (int e = 0; e < 4; e++) {
                        const int m = q0 + m_off + mi * 16 + g + ((e >> 1) << 3);
                        const int n = j0 + nf * 8 + 2 * tq + (e & 1);
                        if (n > m) sacc[mi][nf][e] = -1e30f;
                    }
        }

        // ---- online softmax ----
        #pragma unroll
        for (int mi = 0; mi < 2; mi++) {
            float mx0 = -1e30f, mx1 = -1e30f;
            #pragma unroll
            for (int nf = 0; nf < 8; nf++) {
                mx0 = fmaxf(mx0, fmaxf(sacc[mi][nf][0], sacc[mi][nf][1]));
                mx1 = fmaxf(mx1, fmaxf(sacc[mi][nf][2], sacc[mi][nf][3]));
            }
            mx0 = fmaxf(mx0, __shfl_xor_sync(0xffffffffu, mx0, 1));
            mx0 = fmaxf(mx0, __shfl_xor_sync(0xffffffffu, mx0, 2));
            mx1 = fmaxf(mx1, __shfl_xor_sync(0xffffffffu, mx1, 1));
            mx1 = fmaxf(mx1, __shfl_xor_sync(0xffffffffu, mx1, 2));
            const float mn0 = fmaxf(mrow[mi][0], mx0);
            const float mn1 = fmaxf(mrow[mi][1], mx1);
            const float f0 = __expf(mrow[mi][0] - mn0);
            const float f1 = __expf(mrow[mi][1] - mn1);
            mrow[mi][0] = mn0;
            mrow[mi][1] = mn1;
            float s0 = 0.f, s1 = 0.f;
            #pragma unroll
            for (int nf = 0; nf < 8; nf++) {
                sacc[mi][nf][0] = __expf(sacc[mi][nf][0] - mn0); s0 += sacc[mi][nf][0];
                sacc[mi][nf][1] = __expf(sacc[mi][nf][1] - mn0); s0 += sacc[mi][nf][1];
                sacc[mi][nf][2] = __expf(sacc[mi][nf][2] - mn1); s1 += sacc[mi][nf][2];
                sacc[mi][nf][3] = __expf(sacc[mi][nf][3] - mn1); s1 += sacc[mi][nf][3];
            }
            s0 += __shfl_xor_sync(0xffffffffu, s0, 1);
            s0 += __shfl_xor_sync(0xffffffffu, s0, 2);
            s1 += __shfl_xor_sync(0xffffffffu, s1, 1);
            s1 += __shfl_xor_sync(0xffffffffu, s1, 2);
            lrow[mi][0] = lrow[mi][0] * f0 + s0;
            lrow[mi][1] = lrow[mi][1] * f1 + s1;
            #pragma unroll
            for (int nf = 0; nf < 8; nf++) {
                oacc[mi][nf][0] *= f0;
                oacc[mi][nf][1] *= f0;
                oacc[mi][nf][2] *= f1;
                oacc[mi][nf][3] *= f1;
            }
        }

        // ---- ctx += P V (2-term split) ----
        #pragma unroll
        for (int ks = 0; ks < 4; ks++) {
            uint32_t ph[2][4], pl[2][4];
            #pragma unroll
            for (int mi = 0; mi < 2; mi++) {
                split2h(sacc[mi][2 * ks][0],     sacc[mi][2 * ks][1],     ph[mi][0], pl[mi][0]);
                split2h(sacc[mi][2 * ks][2],     sacc[mi][2 * ks][3],     ph[mi][1], pl[mi][1]);
                split2h(sacc[mi][2 * ks + 1][0], sacc[mi][2 * ks + 1][1], ph[mi][2], pl[mi][2]);
                split2h(sacc[mi][2 * ks + 1][2], sacc[mi][2 * ks + 1][3], ph[mi][3], pl[mi][3]);
            }
            const int kb = 16 * ks + 2 * tq;
            #pragma unroll
            for (int nf = 0; nf < 8; nf++) {
                const int dr = nf * 8 + g;
                uint32_t bhf[2];
                bhf[0] = *(const uint32_t*)&Vh[dr * 72 + kb];
                bhf[1] = *(const uint32_t*)&Vh[dr * 72 + kb + 8];
                #pragma unroll
                for (int mi = 0; mi < 2; mi++) {
                    mma16816(oacc[mi][nf], ph[mi], bhf);
                    mma16816(oacc[mi][nf], pl[mi], bhf);
                }
            }
        }
    }

    // ---- epilogue: normalize, split, store ctx fp16 hi/lo ----
    #pragma unroll
    for (int mi = 0; mi < 2; mi++) {
        const float i0 = 1.f / lrow[mi][0];
        const float i1 = 1.f / lrow[mi][1];
        const int r0 = q0 + m_off + mi * 16 + g;
        #pragma unroll
        for (int nf = 0; nf < 8; nf++) {
            const int col = h * HDIM + nf * 8 + 2 * tq;
            uint32_t hi, lo;
            split2h(oacc[mi][nf][0] * i0, oacc[mi][nf][1] * i0, hi, lo);
            *(uint32_t*)&g_chi[(size_t)(b * SEQ + r0) * DMODEL + col] = hi;
            *(uint32_t*)&g_clo[(size_t)(b * SEQ + r0) * DMODEL + col] = lo;
            split2h(oacc[mi][nf][2] * i1, oacc[mi][nf][3] * i1, hi, lo);
            *(uint32_t*)&g_chi[(size_t)(b * SEQ + r0 + 8) * DMODEL + col] = hi;
            *(uint32_t*)&g_clo[(size_t)(b * SEQ + r0 + 8) * DMODEL + col] = lo;
        }
    }
}

// ---------------------------------------------------------------------------
// Launch
// ---------------------------------------------------------------------------
extern "C" void kernel_launch(void* const* d_in, const int* in_sizes, int n_in,
                              void* d_out, int out_size) {
    const float* x  = (const float*)d_in[0];
    const float* Wq = (const float*)d_in[1];
    const float* Wk = (const float*)d_in[2];
    const float* Wv = (const float*)d_in[3];
    const float* Wo = (const float*)d_in[4];

    float* out  = (float*)d_out;
    float* keys = out + OUT_ELEMS;             // [b,g,s,d]
    float* vals = keys + KV_ELEMS;             // [b,g,s,d]

    cudaFuncSetAttribute((const void*)attn_mma,
                         cudaFuncAttributeMaxDynamicSharedMemorySize, ATT_SMEM);

    // x -> fp16 hi/lo
    cvt_split<0><<<2048, 256>>>(x, (int)(MROWS * DMODEL / 4));
    // Q = x @ Wq^T -> qhi/qlo (fp16)
    cvt_split<1><<<2048, 256>>>(Wq, DMODEL * DMODEL / 4);
    gemm_mma<0, 2><<<dim3(DMODEL / 128, MROWS / 128), 256>>>(nullptr, DMODEL);
    // K = x @ Wk^T -> keys fp32 + khi fp16
    cvt_split<1><<<2048, 256>>>(Wk, NGRP * HDIM * DMODEL / 4);
    gemm_mma<0, 1><<<dim3(NGRP * HDIM / 128, MROWS / 128), 256>>>(keys, NGRP * HDIM);
    // V = x @ Wv^T -> vals fp32 + vthi fp16 (transposed)
    cvt_split<1><<<2048, 256>>>(Wv, NGRP * HDIM * DMODEL / 4);
    gemm_mma<0, 3><<<dim3(NGRP * HDIM / 128, MROWS / 128), 256>>>(vals, NGRP * HDIM);
    // Attention -> chi/clo
    attn_mma<<<dim3(SEQ / 128, 2 * NHEAD), 128, ATT_SMEM>>>();
    // out = ctx @ Wo^T
    cvt_split<1><<<2048, 256>>>(Wo, DMODEL * DMODEL / 4);
    gemm_mma<1, 0><<<dim3(DMODEL / 128, MROWS / 128), 256>>>(out, DMODEL);
}

// round 15
// speedup vs baseline: 4.4873x; 1.3124x over previous
#include <cuda_runtime.h>
#include <cuda_fp16.h>
#include <cstdint>

// B=2, S=2048, D_IN=2048, D_OUT=2048, H=32 heads, G=8 kv groups, R=4, D=64
#define SEQ    2048
#define DMODEL 2048
#define NHEAD  32
#define NGRP   8
#define HDIM   64
#define KDIM   2048

#define OUT_ELEMS  (2ull * SEQ * DMODEL)          // 8388608
#define KV_ELEMS   (2ull * NGRP * SEQ * HDIM)     // 2097152
#define MROWS      (2 * SEQ)                      // 4096
#define NQKV       3072                           // 2048 Q + 512 K + 512 V

// ---------------- device-global scratch (allocation-free rule) --------------
__device__ __half g_xhi[(size_t)MROWS * DMODEL];
__device__ __half g_xlo[(size_t)MROWS * DMODEL];
__device__ __half g_whi[(size_t)NQKV * DMODEL];    // fused QKV weights (or Wo at off 0)
__device__ __half g_qhi[(size_t)MROWS * DMODEL];   // Q proj fp16 hi
__device__ __half g_qlo[(size_t)MROWS * DMODEL];
__device__ __half g_khi[KV_ELEMS];                 // K cache fp16 hi [bg][s][d]
__device__ __half g_vthi[KV_ELEMS];                // V cache fp16 hi transposed [bg][d][s]
__device__ __half g_chi[(size_t)MROWS * DMODEL];   // ctx fp16 hi
__device__ __half g_clo[(size_t)MROWS * DMODEL];

// ---------------- helpers ---------------------------------------------------
__device__ __forceinline__ void split2h(float x, float y, uint32_t& hi, uint32_t& lo) {
    __half hx = __float2half(x), hy = __float2half(y);
    __half lx = __float2half(x - __half2float(hx));
    __half ly = __float2half(y - __half2float(hy));
    __half2 h{hx, hy}, l{lx, ly};
    hi = *(uint32_t*)&h;
    lo = *(uint32_t*)&l;
}

__device__ __forceinline__ void mma16816(float* d, const uint32_t* a, const uint32_t* b) {
    asm volatile(
        "mma.sync.aligned.m16n8k16.row.col.f32.f16.f16.f32 "
        "{%0,%1,%2,%3}, {%4,%5,%6,%7}, {%8,%9}, {%0,%1,%2,%3};\n"
        : "+f"(d[0]), "+f"(d[1]), "+f"(d[2]), "+f"(d[3])
        : "r"(a[0]), "r"(a[1]), "r"(a[2]), "r"(a[3]), "r"(b[0]), "r"(b[1]));
}

__device__ __forceinline__ uint32_t smem_u32(const void* p) {
    uint32_t a;
    asm("{ .reg .u64 t; cvta.to.shared.u64 t, %1; cvt.u32.u64 %0, t; }"
        : "=r"(a) : "l"(p));
    return a;
}
__device__ __forceinline__ void cpa16(uint32_t sdst, const void* g) {
    asm volatile("cp.async.cg.shared.global [%0], [%1], 16;" :: "r"(sdst), "l"(g));
}
__device__ __forceinline__ void cpa_commit() {
    asm volatile("cp.async.commit_group;" ::: "memory");
}
__device__ __forceinline__ void cpa_wait1() {
    asm volatile("cp.async.wait_group 1;" ::: "memory");
}

// ---------------------------------------------------------------------------
// fp32 -> fp16 hi/lo split. DST 0: x (hi+lo). DST 1: W hi-only at offset.
// off4: offset in uint2 (4-half) units.
// ---------------------------------------------------------------------------
template<int DST>
__global__ void __launch_bounds__(256) cvt_split(const float* __restrict__ srcp,
                                                 int n4, size_t off4) {
    const float4* s = (const float4*)srcp;
    uint2* hp = (uint2*)(DST == 0 ? g_xhi : g_whi) + off4;
    uint2* lp = (uint2*)g_xlo;
    for (int i = blockIdx.x * blockDim.x + threadIdx.x; i < n4;
         i += gridDim.x * blockDim.x) {
        float4 v = s[i];
        uint32_t h0, l0, h1, l1;
        split2h(v.x, v.y, h0, l0);
        split2h(v.z, v.w, h1, l1);
        hp[i] = uint2{h0, h1};
        if (DST == 0) lp[i] = uint2{l0, l1};
    }
}

// ---------------------------------------------------------------------------
// Split-fp16 mma.sync GEMM with cp.async 3-stage pipeline.
// C = A @ W^T (Ahi*Whi + Alo*Whi), CTA 128x128, 8 warps, BK=16.
// Stage: 3 tiles x 128 x 24 halves = 18432 B; 3 stages = 55296 B dynamic.
// AB: 0 = A from g_xhi/g_xlo, 1 = A from g_chi/g_clo.
// OM: 0 = out projection: fp32 C row-major [M, 2048].
//     1 = fused QKV: route by n0 (Q: fp16 hi/lo; K: fp32+fp16; V: fp32+fp16^T)
// ---------------------------------------------------------------------------
#define LDK     24
#define TILE_H  (128 * LDK)            // 3072 halves (6144 B)
#define STAGE_H (3 * TILE_H)           // 9216 halves (18432 B)
#define STAGE_B 18432
#define G_SMEM  (3 * STAGE_B)          // 55296 B

template<int AB, int OM>
__global__ void __launch_bounds__(256) gemm_mma(float* __restrict__ P0,
                                                float* __restrict__ P1) {
    extern __shared__ __half smbuf[];

    const int tid  = threadIdx.x;
    const int wid  = tid >> 5;
    const int lane = tid & 31;
    const int g    = lane >> 2;
    const int tq   = lane & 3;
    const int m0 = blockIdx.y * 128;
    const int n0 = blockIdx.x * 128;
    const int m_off = (wid & 3) * 32;
    const int n_off = (wid >> 2) * 64;

    const __half* __restrict__ Ahi = AB ? g_chi : g_xhi;
    const __half* __restrict__ Alo = AB ? g_clo : g_xlo;

    // copy addressing: thread -> (row, 16B chunk); 3 tiles per chunk issue
    const int row = tid >> 1;
    const int ch  = tid & 1;
    const __half* pa_hi = Ahi   + (size_t)(m0 + row) * KDIM + ch * 8;
    const __half* pa_lo = Alo   + (size_t)(m0 + row) * KDIM + ch * 8;
    const __half* pw_hi = g_whi + (size_t)(n0 + row) * KDIM + ch * 8;
    const uint32_t sb = smem_u32(smbuf);
    const uint32_t sd_base = sb + row * 48 + ch * 16;

    float acc[2][8][4] = {};

    // prologue: stages 0 and 1
    #pragma unroll
    for (int p = 0; p < 2; p++) {
        const uint32_t sd = sd_base + p * STAGE_B;
        cpa16(sd + 0 * 6144, pa_hi + p * 16);
        cpa16(sd + 1 * 6144, pa_lo + p * 16);
        cpa16(sd + 2 * 6144, pw_hi + p * 16);
        cpa_commit();
    }

    const int NCH = KDIM / 16;         // 128
    int stage = 0;
    for (int c = 0; c < NCH; c++) {
        cpa_wait1();                    // group c complete (c+1 may be pending)
        __syncthreads();                // publish stage to all warps

        const __half* Sb  = smbuf + stage * STAGE_H;
        const __half* Sah = Sb;
        const __half* Sal = Sb + TILE_H;
        const __half* Swh = Sb + 2 * TILE_H;
        const int kb = 2 * tq;

        uint32_t ah[2][4], al[2][4], wh[8][2];
        #pragma unroll
        for (int mi = 0; mi < 2; mi++) {
            const int r = m_off + mi * 16 + g;
            ah[mi][0] = *(const uint32_t*)&Sah[r * LDK + kb];
            ah[mi][1] = *(const uint32_t*)&Sah[(r + 8) * LDK + kb];
            ah[mi][2] = *(const uint32_t*)&Sah[r * LDK + kb + 8];
            ah[mi][3] = *(const uint32_t*)&Sah[(r + 8) * LDK + kb + 8];
            al[mi][0] = *(const uint32_t*)&Sal[r * LDK + kb];
            al[mi][1] = *(const uint32_t*)&Sal[(r + 8) * LDK + kb];
            al[mi][2] = *(const uint32_t*)&Sal[r * LDK + kb + 8];
            al[mi][3] = *(const uint32_t*)&Sal[(r + 8) * LDK + kb + 8];
        }
        #pragma unroll
        for (int ni = 0; ni < 8; ni++) {
            const int r = n_off + ni * 8 + g;
            wh[ni][0] = *(const uint32_t*)&Swh[r * LDK + kb];
            wh[ni][1] = *(const uint32_t*)&Swh[r * LDK + kb + 8];
        }
        #pragma unroll
        for (int mi = 0; mi < 2; mi++)
            #pragma unroll
            for (int ni = 0; ni < 8; ni++)
                mma16816(acc[mi][ni], ah[mi], wh[ni]);
        #pragma unroll
        for (int mi = 0; mi < 2; mi++)
            #pragma unroll
            for (int ni = 0; ni < 8; ni++)
                mma16816(acc[mi][ni], al[mi], wh[ni]);

        // issue chunk c+2 into stage (c+2)%3 (safe: != compute, != pending)
        if (c + 2 < NCH) {
            const int p = c + 2;
            const uint32_t sd = sd_base + ((p) % 3) * STAGE_B;
            cpa16(sd + 0 * 6144, pa_hi + p * 16);
            cpa16(sd + 1 * 6144, pa_lo + p * 16);
            cpa16(sd + 2 * 6144, pw_hi + p * 16);
        }
        cpa_commit();                   // keep group count in lockstep
        stage = (stage + 1 == 3) ? 0 : stage + 1;
    }

    // ---- epilogue ----
    #pragma unroll
    for (int mi = 0; mi < 2; mi++) {
        #pragma unroll
        for (int ni = 0; ni < 8; ni++) {
            const int nloc = n_off + ni * 8 + 2 * tq;
            #pragma unroll
            for (int h2 = 0; h2 < 2; h2++) {
                const int m = m0 + m_off + mi * 16 + g + h2 * 8;
                const float vx = acc[mi][ni][h2 * 2], vy = acc[mi][ni][h2 * 2 + 1];
                const int n = n0 + nloc;
                if (OM == 0) {
                    *(float2*)&P0[(size_t)m * DMODEL + n] = make_float2(vx, vy);
                } else if (n0 < 2048) {          // Q region
                    uint32_t hi, lo;
                    split2h(vx, vy, hi, lo);
                    *(uint32_t*)&g_qhi[(size_t)m * DMODEL + n] = hi;
                    *(uint32_t*)&g_qlo[(size_t)m * DMODEL + n] = lo;
                } else if (n0 < 2560) {          // K region
                    const int nr = n - 2048;
                    const int bb = m >> 11, s = m & 2047;
                    const size_t bg = (size_t)(bb * NGRP + (nr >> 6));
                    const int d = nr & 63;
                    *(float2*)&P0[(bg * SEQ + s) * HDIM + d] = make_float2(vx, vy);
                    __half2 hh{__float2half(vx), __float2half(vy)};
                    *(__half2*)&g_khi[(bg * SEQ + s) * HDIM + d] = hh;
                } else {                         // V region
                    const int nr = n - 2560;
                    const int bb = m >> 11, s = m & 2047;
                    const size_t bg = (size_t)(bb * NGRP + (nr >> 6));
                    const int d = nr & 63;
                    *(float2*)&P1[(bg * SEQ + s) * HDIM + d] = make_float2(vx, vy);
                    g_vthi[(bg * HDIM + d    ) * SEQ + s] = __float2half(vx);
                    g_vthi[(bg * HDIM + d + 1) * SEQ + s] = __float2half(vy);
                }
            }
        }
    }
}

// ---------------------------------------------------------------------------
// mma.sync flash attention (causal), split-fp16 (2-term), fp32 accumulate.
// CTA = (qt: 128 q rows, b, h). 4 warps, warp owns 32 rows. 64-key tiles.
// Dynamic smem 55296 B: Qhi/Qlo[128][72], Khi[64][72], Vthi[64][72].
// ---------------------------------------------------------------------------
#define ATT_SMEM 55296

__global__ void __launch_bounds__(128) attn_mma() {
    extern __shared__ __half sm[];
    __half* Qh = sm;            // 128*72 = 9216
    __half* Ql = Qh + 9216;
    __half* Kh = Ql + 9216;     // 64*72 = 4608
    __half* Vh = Kh + 4608;     // transposed [d][k]

    const int tid  = threadIdx.x;
    const int wid  = tid >> 5;
    const int lane = tid & 31;
    const int g    = lane >> 2;
    const int tq   = lane & 3;
    const int qt = blockIdx.x;
    const int b  = blockIdx.y >> 5;
    const int h  = blockIdx.y & 31;
    const int grp = h >> 2;
    const int q0 = qt * 128;
    const int m_off = wid * 32;
    const size_t bg = (size_t)(b * NGRP + grp);

    {
        const size_t qb = ((size_t)(b * SEQ + q0)) * DMODEL + h * HDIM;
        for (int i = tid; i < 1024; i += 128) {
            int r = i >> 3, c = (i & 7) * 8;
            *(uint4*)&Qh[r * 72 + c] = *(const uint4*)&g_qhi[qb + (size_t)r * DMODEL + c];
            *(uint4*)&Ql[r * 72 + c] = *(const uint4*)&g_qlo[qb + (size_t)r * DMODEL + c];
        }
    }

    float oacc[2][8][4] = {};
    float mrow[2][2], lrow[2][2];
    #pragma unroll
    for (int mi = 0; mi < 2; mi++) {
        mrow[mi][0] = mrow[mi][1] = -1e30f;
        lrow[mi][0] = lrow[mi][1] = 0.f;
    }

    const __half* Kh_g = g_khi  + bg * SEQ * HDIM;
    const __half* Vh_g = g_vthi + bg * HDIM * SEQ;

    const int njt = 2 * qt + 2;
    for (int jt = 0; jt < njt; jt++) {
        const int j0 = jt * 64;
        __syncthreads();
        for (int i = tid; i < 512; i += 128) {
            int r = i >> 3, c = (i & 7) * 8;
            *(uint4*)&Kh[r * 72 + c] = *(const uint4*)&Kh_g[(size_t)(j0 + r) * HDIM + c];
            *(uint4*)&Vh[r * 72 + c] = *(const uint4*)&Vh_g[(size_t)r * SEQ + j0 + c];
        }
        __syncthreads();

        if (j0 > q0 + m_off + 31) continue;

        // ---- S = Q K^T (2-term split) ----
        float sacc[2][8][4] = {};
        #pragma unroll
        for (int ks = 0; ks < 4; ks++) {
            const int kb = 16 * ks + 2 * tq;
            uint32_t ah[2][4], al[2][4];
            #pragma unroll
            for (int mi = 0; mi < 2; mi++) {
                const int r = m_off + mi * 16 + g;
                ah[mi][0] = *(const uint32_t*)&Qh[r * 72 + kb];
                ah[mi][1] = *(const uint32_t*)&Qh[(r + 8) * 72 + kb];
                ah[mi][2] = *(const uint32_t*)&Qh[r * 72 + kb + 8];
                ah[mi][3] = *(const uint32_t*)&Qh[(r + 8) * 72 + kb + 8];
                al[mi][0] = *(const uint32_t*)&Ql[r * 72 + kb];
                al[mi][1] = *(const uint32_t*)&Ql[(r + 8) * 72 + kb];
                al[mi][2] = *(const uint32_t*)&Ql[r * 72 + kb + 8];
                al[mi][3] = *(const uint32_t*)&Ql[(r + 8) * 72 + kb + 8];
            }
            #pragma unroll
            for (int nf = 0; nf < 8; nf++) {
                const int kr = nf * 8 + g;
                uint32_t bhf[2];
                bhf[0] = *(const uint32_t*)&Kh[kr * 72 + kb];
                bhf[1] = *(const uint32_t*)&Kh[kr * 72 + kb + 8];
                #pragma unroll
                for (int mi = 0; mi < 2; mi++) {
                    mma16816(sacc[mi][nf], ah[mi], bhf);
                    mma16816(sacc[mi][nf], al[mi], bhf);
                }
            }
        }

        // scale + causal mask
        #pragma unroll
        for (int mi = 0; mi < 2; mi++)
            #pragma unroll
            for (int nf = 0; nf < 8; nf++)
                #pragma unroll
                for (int e = 0; e < 4; e++)
                    sacc[mi][nf][e] *= 0.125f;
        if (j0 + 63 > q0 + m_off) {
            #pragma unroll
            for (int mi = 0; mi < 2; mi++)
                #pragma unroll
                for (int nf = 0; nf < 8; nf++)
                    #pragma unroll
                    for (int e = 0; e < 4; e++) {
                        const int m = q0 + m_off + mi * 16 + g + ((e >> 1) << 3);
                        const int n = j0 + nf * 8 + 2 * tq + (e & 1);
                        if (n > m) sacc[mi][nf][e] = -1e30f;
                    }
        }

        // ---- online softmax ----
        #pragma unroll
        for (int mi = 0; mi < 2; mi++) {
            float mx0 = -1e30f, mx1 = -1e30f;
            #pragma unroll
            for (int nf = 0; nf < 8; nf++) {
                mx0 = fmaxf(mx0, fmaxf(sacc[mi][nf][0], sacc[mi][nf][1]));
                mx1 = fmaxf(mx1, fmaxf(sacc[mi][nf][2], sacc[mi][nf][3]));
            }
            mx0 = fmaxf(mx0, __shfl_xor_sync(0xffffffffu, mx0, 1));
            mx0 = fmaxf(mx0, __shfl_xor_sync(0xffffffffu, mx0, 2));
            mx1 = fmaxf(mx1, __shfl_xor_sync(0xffffffffu, mx1, 1));
            mx1 = fmaxf(mx1, __shfl_xor_sync(0xffffffffu, mx1, 2));
            const float mn0 = fmaxf(mrow[mi][0], mx0);
            const float mn1 = fmaxf(mrow[mi][1], mx1);
            const float f0 = __expf(mrow[mi][0] - mn0);
            const float f1 = __expf(mrow[mi][1] - mn1);
            mrow[mi][0] = mn0;
            mrow[mi][1] = mn1;
            float s0 = 0.f, s1 = 0.f;
            #pragma unroll
            for (int nf = 0; nf < 8; nf++) {
                sacc[mi][nf][0] = __expf(sacc[mi][nf][0] - mn0); s0 += sacc[mi][nf][0];
                sacc[mi][nf][1] = __expf(sacc[mi][nf][1] - mn0); s0 += sacc[mi][nf][1];
                sacc[mi][nf][2] = __expf(sacc[mi][nf][2] - mn1); s1 += sacc[mi][nf][2];
                sacc[mi][nf][3] = __expf(sacc[mi][nf][3] - mn1); s1 += sacc[mi][nf][3];
            }
            s0 += __shfl_xor_sync(0xffffffffu, s0, 1);
            s0 += __shfl_xor_sync(0xffffffffu, s0, 2);
            s1 += __shfl_xor_sync(0xffffffffu, s1, 1);
            s1 += __shfl_xor_sync(0xffffffffu, s1, 2);
            lrow[mi][0] = lrow[mi][0] * f0 + s0;
            lrow[mi][1] = lrow[mi][1] * f1 + s1;
            #pragma unroll
            for (int nf = 0; nf < 8; nf++) {
                oacc[mi][nf][0] *= f0;
                oacc[mi][nf][1] *= f0;
                oacc[mi][nf][2] *= f1;
                oacc[mi][nf][3] *= f1;
            }
        }

        // ---- ctx += P V (2-term split) ----
        #pragma unroll
        for (int ks = 0; ks < 4; ks++) {
            uint32_t ph[2][4], pl[2][4];
            #pragma unroll
            for (int mi = 0; mi < 2; mi++) {
                split2h(sacc[mi][2 * ks][0],     sacc[mi][2 * ks][1],     ph[mi][0], pl[mi][0]);
                split2h(sacc[mi][2 * ks][2],     sacc[mi][2 * ks][3],     ph[mi][1], pl[mi][1]);
                split2h(sacc[mi][2 * ks + 1][0], sacc[mi][2 * ks + 1][1], ph[mi][2], pl[mi][2]);
                split2h(sacc[mi][2 * ks + 1][2], sacc[mi][2 * ks + 1][3], ph[mi][3], pl[mi][3]);
            }
            const int kb = 16 * ks + 2 * tq;
            #pragma unroll
            for (int nf = 0; nf < 8; nf++) {
                const int dr = nf * 8 + g;
                uint32_t bhf[2];
                bhf[0] = *(const uint32_t*)&Vh[dr * 72 + kb];
                bhf[1] = *(const uint32_t*)&Vh[dr * 72 + kb + 8];
                #pragma unroll
                for (int mi = 0; mi < 2; mi++) {
                    mma16816(oacc[mi][nf], ph[mi], bhf);
                    mma16816(oacc[mi][nf], pl[mi], bhf);
                }
            }
        }
    }

    // ---- epilogue: normalize, split, store ctx fp16 hi/lo ----
    #pragma unroll
    for (int mi = 0; mi < 2; mi++) {
        const float i0 = 1.f / lrow[mi][0];
        const float i1 = 1.f / lrow[mi][1];
        const int r0 = q0 + m_off + mi * 16 + g;
        #pragma unroll
        for (int nf = 0; nf < 8; nf++) {
            const int col = h * HDIM + nf * 8 + 2 * tq;
            uint32_t hi, lo;
            split2h(oacc[mi][nf][0] * i0, oacc[mi][nf][1] * i0, hi, lo);
            *(uint32_t*)&g_chi[(size_t)(b * SEQ + r0) * DMODEL + col] = hi;
            *(uint32_t*)&g_clo[(size_t)(b * SEQ + r0) * DMODEL + col] = lo;
            split2h(oacc[mi][nf][2] * i1, oacc[mi][nf][3] * i1, hi, lo);
            *(uint32_t*)&g_chi[(size_t)(b * SEQ + r0 + 8) * DMODEL + col] = hi;
            *(uint32_t*)&g_clo[(size_t)(b * SEQ + r0 + 8) * DMODEL + col] = lo;
        }
    }
}

// ---------------------------------------------------------------------------
// Launch
// ---------------------------------------------------------------------------
extern "C" void kernel_launch(void* const* d_in, const int* in_sizes, int n_in,
                              void* d_out, int out_size) {
    const float* x  = (const float*)d_in[0];
    const float* Wq = (const float*)d_in[1];
    const float* Wk = (const float*)d_in[2];
    const float* Wv = (const float*)d_in[3];
    const float* Wo = (const float*)d_in[4];

    float* out  = (float*)d_out;
    float* keys = out + OUT_ELEMS;             // [b,g,s,d]
    float* vals = keys + KV_ELEMS;             // [b,g,s,d]

    cudaFuncSetAttribute((const void*)attn_mma,
                         cudaFuncAttributeMaxDynamicSharedMemorySize, ATT_SMEM);
    cudaFuncSetAttribute((const void*)gemm_mma<0, 1>,
                         cudaFuncAttributeMaxDynamicSharedMemorySize, G_SMEM);
    cudaFuncSetAttribute((const void*)gemm_mma<1, 0>,
                         cudaFuncAttributeMaxDynamicSharedMemorySize, G_SMEM);

    // x -> fp16 hi/lo ; Wq/Wk/Wv -> fused weight buffer (hi only)
    cvt_split<0><<<2048, 256>>>(x, (int)(MROWS * DMODEL / 4), 0);
    cvt_split<1><<<2048, 256>>>(Wq, DMODEL * DMODEL / 4, 0);
    cvt_split<1><<<1024, 256>>>(Wk, 512 * DMODEL / 4, (size_t)2048 * DMODEL / 4);
    cvt_split<1><<<1024, 256>>>(Wv, 512 * DMODEL / 4, (size_t)2560 * DMODEL / 4);
    // Fused QKV projection (Q->qhi/qlo, K->keys+khi, V->vals+vthi)
    gemm_mma<0, 1><<<dim3(NQKV / 128, MROWS / 128), 256, G_SMEM>>>(keys, vals);
    // Attention -> chi/clo
    attn_mma<<<dim3(SEQ / 128, 2 * NHEAD), 128, ATT_SMEM>>>();
    // out = ctx @ Wo^T
    cvt_split<1><<<2048, 256>>>(Wo, DMODEL * DMODEL / 4, 0);
    gemm_mma<1, 0><<<dim3(DMODEL / 128, MROWS / 128), 256, G_SMEM>>>(out, nullptr);
}